// round 1
// baseline (speedup 1.0000x reference)
#include <cuda_runtime.h>

#define B_  1024
#define T_  256
#define D_  64
#define H_  128
#define GC  384   // 2H gate cols + H cand cols

// Scratch: x-projections (gate 256 cols, cand 128 cols) per (b,t). ~402MB static.
__device__ float g_xproj[(size_t)B_ * T_ * GC];
__device__ int   g_order[B_];

// ---------------- packed f32x2 helpers (sm_103a) ----------------
typedef unsigned long long f32x2;
__device__ __forceinline__ f32x2 pack2(float lo, float hi) {
    f32x2 r; asm("mov.b64 %0, {%1,%2};" : "=l"(r) : "f"(lo), "f"(hi)); return r;
}
__device__ __forceinline__ float2 unpack2(f32x2 v) {
    float2 f; asm("mov.b64 {%0,%1}, %2;" : "=f"(f.x), "=f"(f.y) : "l"(v)); return f;
}
__device__ __forceinline__ f32x2 fma2(f32x2 a, f32x2 b, f32x2 c) {
    f32x2 d; asm("fma.rn.f32x2 %0, %1, %2, %3;" : "=l"(d) : "l"(a), "l"(b), "l"(c)); return d;
}

__device__ __forceinline__ float sigmoidf_(float x) {
    return __fdividef(1.0f, 1.0f + __expf(-x));
}
__device__ __forceinline__ float tanhf_(float x) {
    // tanh(x) = 1 - 2/(exp(2x)+1); saturates correctly at +/-inf
    return 1.0f - __fdividef(2.0f, __expf(2.0f * x) + 1.0f);
}

// ---------------- counting sort of rows by seq_len (descending) ----------------
__global__ void sort_kernel(const int* __restrict__ seq_lens) {
    __shared__ int hist[T_];
    __shared__ int offs[T_];
    int tid = threadIdx.x;
    for (int i = tid; i < T_; i += 256) hist[i] = 0;
    __syncthreads();
    for (int i = tid; i < B_; i += 256) {
        int key = T_ - 1 - seq_lens[i];   // descending by len
        atomicAdd(&hist[key], 1);
    }
    __syncthreads();
    if (tid == 0) {
        int s = 0;
        for (int k = 0; k < T_; k++) { offs[k] = s; s += hist[k]; }
    }
    __syncthreads();
    for (int i = tid; i < T_; i += 256) hist[i] = 0;
    __syncthreads();
    for (int i = tid; i < B_; i += 256) {
        int key = T_ - 1 - seq_lens[i];
        int pos = offs[key] + atomicAdd(&hist[key], 1);
        g_order[pos] = i;
    }
}

// ---------------- Phase A: xproj[b,t,:] = emb[item[b,t]] @ [Wgx|Wcx] + [gb|cb] --------
// grid: 4096 blocks = (b, t-tile of 64). 128 threads. Skips fully-masked tiles.
__global__ void __launch_bounds__(128, 1) xproj_kernel(
    const int*   __restrict__ item_his,
    const int*   __restrict__ seq_lens,
    const float* __restrict__ emb,
    const float* __restrict__ gk, const float* __restrict__ gb,
    const float* __restrict__ ck, const float* __restrict__ cb)
{
    extern __shared__ float smem[];
    float* sW    = smem;                 // [64][384]
    float* sBias = sW + 64 * GC;         // [384]
    float* sX    = sBias + GC;           // x transposed: [k=64][r stride 72]
    const int XS = 72;                   // row stride (floats), keeps 16B alignment

    int b  = blockIdx.x >> 2;
    int t0 = (blockIdx.x & 3) << 6;
    int len = seq_lens[b];
    if (t0 >= len) return;               // whole tile past sequence end

    int tid = threadIdx.x;

    // load x-part weights: gate rows 0..63 of gate_kernel / cand_kernel
    for (int i = tid; i < 64 * GC; i += 128) {
        int k = i / GC, j = i - k * GC;
        sW[i] = (j < 256) ? gk[k * 256 + j] : ck[k * 128 + (j - 256)];
    }
    for (int j = tid; j < GC; j += 128) sBias[j] = (j < 256) ? gb[j] : cb[j - 256];

    // gather embedding rows, store transposed sX[k][r]
    {
        int r  = tid & 63;
        int k0 = (tid >> 6) << 5;        // 0 or 32
        int item = item_his[b * T_ + t0 + r];
        const float4* erow = reinterpret_cast<const float4*>(emb + (size_t)item * D_ + k0);
        #pragma unroll
        for (int i = 0; i < 8; i++) {
            float4 v = erow[i];
            int k = k0 + i * 4;
            sX[(k + 0) * XS + r] = v.x;
            sX[(k + 1) * XS + r] = v.y;
            sX[(k + 2) * XS + r] = v.z;
            sX[(k + 3) * XS + r] = v.w;
        }
    }
    __syncthreads();

    float bias0 = sBias[tid], bias1 = sBias[tid + 128], bias2 = sBias[tid + 256];
    float* outp = g_xproj + ((size_t)b * T_ + t0) * GC;

    for (int r0 = 0; r0 < 64; r0 += 8) {           // 8 rows per pass (4 packed pairs)
        f32x2 acc[3][4];
        #pragma unroll
        for (int c = 0; c < 3; c++)
            #pragma unroll
            for (int p = 0; p < 4; p++) acc[c][p] = 0ull;

        #pragma unroll 4
        for (int k = 0; k < 64; k++) {
            float4 h0 = *reinterpret_cast<const float4*>(&sX[k * XS + r0]);
            float4 h1 = *reinterpret_cast<const float4*>(&sX[k * XS + r0 + 4]);
            f32x2 hp[4] = { pack2(h0.x, h0.y), pack2(h0.z, h0.w),
                            pack2(h1.x, h1.y), pack2(h1.z, h1.w) };
            const float* wrow = sW + k * GC + tid;
            float w0s = wrow[0], w1s = wrow[128], w2s = wrow[256];
            f32x2 w0 = pack2(w0s, w0s);
            f32x2 w1 = pack2(w1s, w1s);
            f32x2 w2 = pack2(w2s, w2s);
            #pragma unroll
            for (int p = 0; p < 4; p++) {
                acc[0][p] = fma2(hp[p], w0, acc[0][p]);
                acc[1][p] = fma2(hp[p], w1, acc[1][p]);
                acc[2][p] = fma2(hp[p], w2, acc[2][p]);
            }
        }
        #pragma unroll
        for (int p = 0; p < 4; p++) {
            float2 a0 = unpack2(acc[0][p]);
            float2 a1 = unpack2(acc[1][p]);
            float2 a2 = unpack2(acc[2][p]);
            float* o0 = outp + (size_t)(r0 + 2 * p) * GC;
            float* o1 = o0 + GC;
            o0[tid]       = a0.x + bias0;  o1[tid]       = a0.y + bias0;
            o0[tid + 128] = a1.x + bias1;  o1[tid + 128] = a1.y + bias1;
            o0[tid + 256] = a2.x + bias2;  o1[tid + 256] = a2.y + bias2;
        }
    }
}

// ---------------- Phase B: sequential GRU. 256 blocks x 4 rows, 128 threads ----------
// Recurrent weights [128][384] fp32 resident in SMEM (~196KB). h transposed in SMEM.
__global__ void __launch_bounds__(128, 1) gru_kernel(
    const int*   __restrict__ seq_lens,
    const float* __restrict__ gk,
    const float* __restrict__ ck,
    float*       __restrict__ out)
{
    extern __shared__ float smem[];
    float* sW = smem;              // [128][384]
    float* ht = sW + 128 * GC;     // h transposed [k=128][r=4]
    float* rt = ht + 128 * 4;      // (r gate * h) transposed [128][4]

    int tid = threadIdx.x;

    // recurrent weights: rows 64..191 of gate_kernel / cand_kernel
    for (int i = tid; i < 128 * GC; i += 128) {
        int k = i / GC, j = i - k * GC;
        sW[i] = (j < 256) ? gk[(64 + k) * 256 + j] : ck[(64 + k) * 128 + (j - 256)];
    }

    int rowb[4], lens[4], maxlen = 0;
    #pragma unroll
    for (int r = 0; r < 4; r++) {
        int b = g_order[blockIdx.x * 4 + r];
        rowb[r] = b;
        lens[r] = seq_lens[b];
        maxlen  = max(maxlen, lens[r]);
    }

    #pragma unroll
    for (int r = 0; r < 4; r++) { ht[tid * 4 + r] = 0.0f; rt[tid * 4 + r] = 0.0f; }
    __syncthreads();

    const size_t xstride = (size_t)T_ * GC;

    for (int t = 0; t < maxlen; t++) {
        // prefetch x-projection contributions (global; hidden under gate GEMM)
        float xg0[4], xg1[4], xc[4];
        #pragma unroll
        for (int r = 0; r < 4; r++) {
            if (t < lens[r]) {
                const float* xp = g_xproj + (size_t)rowb[r] * xstride + (size_t)t * GC;
                xg0[r] = xp[tid]; xg1[r] = xp[tid + 128]; xc[r] = xp[tid + 256];
            } else { xg0[r] = 0.0f; xg1[r] = 0.0f; xc[r] = 0.0f; }
        }

        // gate GEMM: cols (tid) -> r-gate, (tid+128) -> u-gate, all 4 rows (2 pairs)
        f32x2 a00 = 0ull, a01 = 0ull, a10 = 0ull, a11 = 0ull;
        #pragma unroll 4
        for (int k = 0; k < 128; k++) {
            float4 h = *reinterpret_cast<const float4*>(&ht[k * 4]);
            f32x2 hp0 = pack2(h.x, h.y), hp1 = pack2(h.z, h.w);
            const float* wrow = sW + k * GC + tid;
            float w0s = wrow[0], w1s = wrow[128];
            f32x2 w0 = pack2(w0s, w0s);
            f32x2 w1 = pack2(w1s, w1s);
            a00 = fma2(hp0, w0, a00);  a01 = fma2(hp1, w0, a01);
            a10 = fma2(hp0, w1, a10);  a11 = fma2(hp1, w1, a11);
        }

        // elementwise gates; write rt (this thread owns k=tid row of ht/rt)
        float hold[4], u[4];
        #pragma unroll
        for (int r = 0; r < 4; r++) hold[r] = ht[tid * 4 + r];
        {
            float2 g0 = unpack2(a00), g1 = unpack2(a01);
            float2 u0 = unpack2(a10), u1 = unpack2(a11);
            float gr[4] = { g0.x, g0.y, g1.x, g1.y };
            float gu[4] = { u0.x, u0.y, u1.x, u1.y };
            #pragma unroll
            for (int r = 0; r < 4; r++) {
                float rv = sigmoidf_(gr[r] + xg0[r]);
                u[r]     = sigmoidf_(gu[r] + xg1[r]);
                rt[tid * 4 + r] = rv * hold[r];
            }
        }
        __syncthreads();   // rt ready for all threads

        // candidate GEMM: col tid, 4 rows
        f32x2 c0 = 0ull, c1 = 0ull;
        #pragma unroll 4
        for (int k = 0; k < 128; k++) {
            float4 rh = *reinterpret_cast<const float4*>(&rt[k * 4]);
            float ws = sW[k * GC + 256 + tid];
            f32x2 wp = pack2(ws, ws);
            c0 = fma2(pack2(rh.x, rh.y), wp, c0);
            c1 = fma2(pack2(rh.z, rh.w), wp, c1);
        }
        {
            float2 cc0 = unpack2(c0), cc1 = unpack2(c1);
            float cv[4] = { cc0.x, cc0.y, cc1.x, cc1.y };
            #pragma unroll
            for (int r = 0; r < 4; r++) {
                if (t < lens[r]) {
                    float c = tanhf_(cv[r] + xc[r]);
                    ht[tid * 4 + r] = u[r] * hold[r] + (1.0f - u[r]) * c;
                }
            }
        }
        __syncthreads();   // ht ready for next step's gate GEMM
    }

    #pragma unroll
    for (int r = 0; r < 4; r++)
        out[(size_t)rowb[r] * H_ + tid] = ht[tid * 4 + r];
}

// ---------------- launch ----------------
static const int A_SMEM = (64 * GC + GC + 64 * 72) * 4;        // 118272 B
static const int B_SMEM = (128 * GC + 128 * 4 + 128 * 4) * 4;  // 200704 B

extern "C" void kernel_launch(void* const* d_in, const int* in_sizes, int n_in,
                              void* d_out, int out_size) {
    const int*   item_his = (const int*)  d_in[0];
    const int*   seq_lens = (const int*)  d_in[1];
    const float* emb      = (const float*)d_in[2];
    const float* gk       = (const float*)d_in[3];
    const float* gb       = (const float*)d_in[4];
    const float* ck       = (const float*)d_in[5];
    const float* cb       = (const float*)d_in[6];
    float*       out      = (float*)d_out;

    cudaFuncSetAttribute(xproj_kernel, cudaFuncAttributeMaxDynamicSharedMemorySize, A_SMEM);
    cudaFuncSetAttribute(gru_kernel,   cudaFuncAttributeMaxDynamicSharedMemorySize, B_SMEM);

    sort_kernel<<<1, 256>>>(seq_lens);
    xproj_kernel<<<B_ * (T_ / 64), 128, A_SMEM>>>(item_his, seq_lens, emb, gk, gb, ck, cb);
    gru_kernel<<<B_ / 4, 128, B_SMEM>>>(seq_lens, gk, ck, out);
}

// round 2
// speedup vs baseline: 1.0874x; 1.0874x over previous
#include <cuda_runtime.h>

#define B_    1024
#define T_    256
#define D_    64
#define H_    128
#define GC    384   // 2H gate cols + H cand cols
#define WS    132   // padded k-stride for transposed weights (16B aligned, conflict-free LDS.128)
#define RMAX  16
#define TH4   167   // len >= TH4 -> 4 rows/CTA
#define TH8   88    // len >= TH8 -> 8 rows/CTA, else 16

// Scratch: x-projections (gate 256 cols, cand 128 cols) per (b,t). ~402MB static.
__device__ float g_xproj[(size_t)B_ * T_ * GC];
__device__ int   g_order[B_];
__device__ int4  g_groups[B_ / 4 + 8];   // {pos, bucket, nrows, maxlen}
__device__ int   g_ngroups;

// ---------------- packed f32x2 helpers (sm_103a) ----------------
typedef unsigned long long f32x2;
__device__ __forceinline__ f32x2 pack2(float lo, float hi) {
    f32x2 r; asm("mov.b64 %0, {%1,%2};" : "=l"(r) : "f"(lo), "f"(hi)); return r;
}
__device__ __forceinline__ float2 unpack2(f32x2 v) {
    float2 f; asm("mov.b64 {%0,%1}, %2;" : "=f"(f.x), "=f"(f.y) : "l"(v)); return f;
}
__device__ __forceinline__ f32x2 fma2(f32x2 a, f32x2 b, f32x2 c) {
    f32x2 d; asm("fma.rn.f32x2 %0, %1, %2, %3;" : "=l"(d) : "l"(a), "l"(b), "l"(c)); return d;
}

__device__ __forceinline__ float sigmoidf_(float x) {
    return __fdividef(1.0f, 1.0f + __expf(-x));
}
__device__ __forceinline__ float tanhf_(float x) {
    return 1.0f - __fdividef(2.0f, __expf(2.0f * x) + 1.0f);
}

// ---------------- counting sort (desc by len) + load-balanced grouping ----------------
__global__ void sort_group_kernel(const int* __restrict__ seq_lens) {
    __shared__ int hist[T_];
    __shared__ int offs[T_];
    __shared__ int slens[B_];
    int tid = threadIdx.x;
    for (int i = tid; i < T_; i += 256) hist[i] = 0;
    __syncthreads();
    for (int i = tid; i < B_; i += 256) {
        int key = T_ - 1 - seq_lens[i];
        atomicAdd(&hist[key], 1);
    }
    __syncthreads();
    if (tid == 0) {
        int s = 0;
        for (int k = 0; k < T_; k++) { offs[k] = s; s += hist[k]; }
    }
    __syncthreads();
    for (int i = tid; i < T_; i += 256) hist[i] = 0;
    __syncthreads();
    for (int i = tid; i < B_; i += 256) {
        int key = T_ - 1 - seq_lens[i];
        int pos = offs[key] + atomicAdd(&hist[key], 1);
        g_order[pos] = i;
    }
    __syncthreads();
    // stage sorted lengths into smem for the serial grouping walk
    for (int i = tid; i < B_; i += 256) slens[i] = seq_lens[g_order[i]];
    __syncthreads();
    if (tid == 0) {
        int pos = 0, g = 0;
        while (pos < B_) {
            int L = slens[pos];
            int R = (L >= TH4) ? 4 : (L >= TH8) ? 8 : 16;
            int nr = min(R, B_ - pos);
            g_groups[g] = make_int4(pos, R, nr, L);
            pos += nr; g++;
        }
        g_ngroups = g;
    }
}

// ---------------- Phase A: xproj[b,t,:] = emb[item[b,t]] @ [Wgx|Wcx] + [gb|cb] --------
__global__ void __launch_bounds__(128, 1) xproj_kernel(
    const int*   __restrict__ item_his,
    const int*   __restrict__ seq_lens,
    const float* __restrict__ emb,
    const float* __restrict__ gk, const float* __restrict__ gb,
    const float* __restrict__ ck, const float* __restrict__ cb)
{
    extern __shared__ float smem[];
    float* sW    = smem;                 // [64][384]
    float* sBias = sW + 64 * GC;         // [384]
    float* sX    = sBias + GC;           // x transposed: [k=64][r stride 72]
    const int XS = 72;

    int b  = blockIdx.x >> 2;
    int t0 = (blockIdx.x & 3) << 6;
    int len = seq_lens[b];
    if (t0 >= len) return;

    int tid = threadIdx.x;

    for (int i = tid; i < 64 * GC; i += 128) {
        int k = i / GC, j = i - k * GC;
        sW[i] = (j < 256) ? gk[k * 256 + j] : ck[k * 128 + (j - 256)];
    }
    for (int j = tid; j < GC; j += 128) sBias[j] = (j < 256) ? gb[j] : cb[j - 256];

    {
        int r  = tid & 63;
        int k0 = (tid >> 6) << 5;
        int item = item_his[b * T_ + t0 + r];
        const float4* erow = reinterpret_cast<const float4*>(emb + (size_t)item * D_ + k0);
        #pragma unroll
        for (int i = 0; i < 8; i++) {
            float4 v = erow[i];
            int k = k0 + i * 4;
            sX[(k + 0) * XS + r] = v.x;
            sX[(k + 1) * XS + r] = v.y;
            sX[(k + 2) * XS + r] = v.z;
            sX[(k + 3) * XS + r] = v.w;
        }
    }
    __syncthreads();

    float bias0 = sBias[tid], bias1 = sBias[tid + 128], bias2 = sBias[tid + 256];
    float* outp = g_xproj + ((size_t)b * T_ + t0) * GC;

    for (int r0 = 0; r0 < 64; r0 += 8) {
        f32x2 acc[3][4];
        #pragma unroll
        for (int c = 0; c < 3; c++)
            #pragma unroll
            for (int p = 0; p < 4; p++) acc[c][p] = 0ull;

        #pragma unroll 4
        for (int k = 0; k < 64; k++) {
            float4 h0 = *reinterpret_cast<const float4*>(&sX[k * XS + r0]);
            float4 h1 = *reinterpret_cast<const float4*>(&sX[k * XS + r0 + 4]);
            f32x2 hp[4] = { pack2(h0.x, h0.y), pack2(h0.z, h0.w),
                            pack2(h1.x, h1.y), pack2(h1.z, h1.w) };
            const float* wrow = sW + k * GC + tid;
            float w0s = wrow[0], w1s = wrow[128], w2s = wrow[256];
            f32x2 w0 = pack2(w0s, w0s);
            f32x2 w1 = pack2(w1s, w1s);
            f32x2 w2 = pack2(w2s, w2s);
            #pragma unroll
            for (int p = 0; p < 4; p++) {
                acc[0][p] = fma2(hp[p], w0, acc[0][p]);
                acc[1][p] = fma2(hp[p], w1, acc[1][p]);
                acc[2][p] = fma2(hp[p], w2, acc[2][p]);
            }
        }
        #pragma unroll
        for (int p = 0; p < 4; p++) {
            float2 a0 = unpack2(acc[0][p]);
            float2 a1 = unpack2(acc[1][p]);
            float2 a2 = unpack2(acc[2][p]);
            float* o0 = outp + (size_t)(r0 + 2 * p) * GC;
            float* o1 = o0 + GC;
            o0[tid]       = a0.x + bias0;  o1[tid]       = a0.y + bias0;
            o0[tid + 128] = a1.x + bias1;  o1[tid + 128] = a1.y + bias1;
            o0[tid + 256] = a2.x + bias2;  o1[tid + 256] = a2.y + bias2;
        }
    }
}

// ---------------- Phase B: sequential GRU, variable rows/CTA, 256 threads -------------
// smem: weights transposed [col][k] stride WS; ht/rt/pc as [r][128].
template<int R>
__device__ __forceinline__ void gru_run(
    const float* __restrict__ sWt, float* __restrict__ ht, float* __restrict__ rt,
    float* __restrict__ pc, const int* __restrict__ srow, const int* __restrict__ slen,
    int nr, int maxlen, float* __restrict__ out)
{
    int tid = threadIdx.x;
    int j   = tid & 127;
    bool hi = tid >= 128;   // uniform per warp (warps 0-3 lo, 4-7 hi)

    const float* xb[R];
    int len_[R];
    #pragma unroll
    for (int r = 0; r < R; r++) {
        int row = (r < nr) ? srow[r] : 0;
        len_[r] = slen[r];             // 0 for r >= nr (set by caller)
        xb[r]   = g_xproj + (size_t)row * (T_ * GC);
    }

    const float* wg = sWt + tid * WS;                       // gate col = tid
    const float* wc = sWt + (256 + j) * WS + (hi ? 64 : 0); // cand col = j, k-split

    float u_[R];

    for (int t = 0; t < maxlen; t++) {
        // prefetch x-projections (consumed after the gate GEMM -> latency hidden)
        float px0[R], px1[R];
        #pragma unroll
        for (int r = 0; r < R; r++) {
            px0[r] = 0.0f; px1[r] = 0.0f;
            if (t < len_[r]) {
                const float* xp = xb[r] + (size_t)t * GC;
                if (!hi) { px0[r] = xp[j]; }
                else     { px0[r] = xp[128 + j]; px1[r] = xp[256 + j]; }
            }
        }

        // ---- gate GEMM: col tid, R rows, k packed in pairs ----
        f32x2 acc[R];
        #pragma unroll
        for (int r = 0; r < R; r++) acc[r] = 0ull;
        #pragma unroll 8
        for (int kk = 0; kk < 32; kk++) {               // 4 k per iter
            ulonglong2 w = *reinterpret_cast<const ulonglong2*>(wg + kk * 4);
            #pragma unroll
            for (int r = 0; r < R; r++) {
                ulonglong2 h = *reinterpret_cast<const ulonglong2*>(ht + r * 128 + kk * 4);
                acc[r] = fma2(h.x, w.x, acc[r]);
                acc[r] = fma2(h.y, w.y, acc[r]);
            }
        }

        // ---- gate elementwise ----
        #pragma unroll
        for (int r = 0; r < R; r++) {
            float2 a = unpack2(acc[r]);
            float s = sigmoidf_(a.x + a.y + px0[r]);
            if (!hi) rt[r * 128 + j] = s * ht[r * 128 + j];
            else     u_[r] = s;
        }
        __syncthreads();

        // ---- cand GEMM: col j, k-split halves ----
        f32x2 cacc[R];
        #pragma unroll
        for (int r = 0; r < R; r++) cacc[r] = 0ull;
        const float* rbase = rt + (hi ? 64 : 0);
        #pragma unroll 8
        for (int kk = 0; kk < 16; kk++) {               // 4 k per iter, 64 k per half
            ulonglong2 w = *reinterpret_cast<const ulonglong2*>(wc + kk * 4);
            #pragma unroll
            for (int r = 0; r < R; r++) {
                ulonglong2 h = *reinterpret_cast<const ulonglong2*>(rbase + r * 128 + kk * 4);
                cacc[r] = fma2(h.x, w.x, cacc[r]);
                cacc[r] = fma2(h.y, w.y, cacc[r]);
            }
        }
        if (!hi) {
            #pragma unroll
            for (int r = 0; r < R; r++) {
                float2 a = unpack2(cacc[r]);
                pc[r * 128 + j] = a.x + a.y;
            }
        }
        __syncthreads();

        // ---- final update (hi threads own hidden unit j) ----
        if (hi) {
            #pragma unroll
            for (int r = 0; r < R; r++) {
                if (t < len_[r]) {
                    float2 a = unpack2(cacc[r]);
                    float c = tanhf_(a.x + a.y + pc[r * 128 + j] + px1[r]);
                    float hold = ht[r * 128 + j];
                    ht[r * 128 + j] = u_[r] * hold + (1.0f - u_[r]) * c;
                }
            }
        }
        __syncthreads();
    }

    if (!hi) {
        #pragma unroll
        for (int r = 0; r < R; r++)
            if (r < nr) out[(size_t)srow[r] * H_ + j] = ht[r * 128 + j];
    }
}

__global__ void __launch_bounds__(256, 1) gru_kernel2(
    const int*   __restrict__ seq_lens,
    const float* __restrict__ gk,
    const float* __restrict__ ck,
    float*       __restrict__ out)
{
    extern __shared__ float smem[];
    float* sWt = smem;                    // [384][WS]
    float* ht  = sWt + GC * WS;           // [RMAX][128]
    float* rt  = ht + RMAX * 128;
    float* pc  = rt + RMAX * 128;
    int*   srow = (int*)(pc + RMAX * 128);
    int*   slen = srow + RMAX;

    int bid = blockIdx.x;
    if (bid >= g_ngroups) return;
    int4 grp = g_groups[bid];   // {pos, bucket, nrows, maxlen}
    int tid = threadIdx.x;

    // weights transposed: sWt[col][k] = W[64+k][col] (coalesced global reads)
    for (int i = tid; i < GC * H_; i += 256) {
        int k = i / GC, col = i - k * GC;
        sWt[col * WS + k] = (col < 256) ? gk[(64 + k) * 256 + col]
                                        : ck[(64 + k) * 128 + (col - 256)];
    }
    for (int i = tid; i < RMAX * 128; i += 256) { ht[i] = 0.0f; rt[i] = 0.0f; pc[i] = 0.0f; }
    if (tid < RMAX) {
        int r = tid;
        int row = (r < grp.z) ? g_order[grp.x + r] : 0;
        srow[r] = row;
        slen[r] = (r < grp.z) ? seq_lens[row] : 0;
    }
    __syncthreads();

    if (grp.y == 4)      gru_run<4> (sWt, ht, rt, pc, srow, slen, grp.z, grp.w, out);
    else if (grp.y == 8) gru_run<8> (sWt, ht, rt, pc, srow, slen, grp.z, grp.w, out);
    else                 gru_run<16>(sWt, ht, rt, pc, srow, slen, grp.z, grp.w, out);
}

// ---------------- launch ----------------
static const int A_SMEM = (64 * GC + GC + 64 * 72) * 4;                       // 118272 B
static const int B_SMEM = (GC * WS + 3 * RMAX * 128) * 4 + 2 * RMAX * 4;      // 227456 B

extern "C" void kernel_launch(void* const* d_in, const int* in_sizes, int n_in,
                              void* d_out, int out_size) {
    const int*   item_his = (const int*)  d_in[0];
    const int*   seq_lens = (const int*)  d_in[1];
    const float* emb      = (const float*)d_in[2];
    const float* gk       = (const float*)d_in[3];
    const float* gb       = (const float*)d_in[4];
    const float* ck       = (const float*)d_in[5];
    const float* cb       = (const float*)d_in[6];
    float*       out      = (float*)d_out;

    cudaFuncSetAttribute(xproj_kernel, cudaFuncAttributeMaxDynamicSharedMemorySize, A_SMEM);
    cudaFuncSetAttribute(gru_kernel2,  cudaFuncAttributeMaxDynamicSharedMemorySize, B_SMEM);

    sort_group_kernel<<<1, 256>>>(seq_lens);
    xproj_kernel<<<B_ * (T_ / 64), 128, A_SMEM>>>(item_his, seq_lens, emb, gk, gb, ck, cb);
    gru_kernel2<<<B_ / 4, 256, B_SMEM>>>(seq_lens, gk, ck, out);
}

// round 3
// speedup vs baseline: 1.1850x; 1.0898x over previous
#include <cuda_runtime.h>

#define B_    1024
#define T_    256
#define D_    64
#define H_    128
#define GC    384   // 2H gate cols + H cand cols
#define WS    132   // padded k-stride (gru weights), conflict-free LDS.128
#define AWS   68    // padded k-stride (xproj weights, K=64)
#define RMAX  8
#define TH4   170   // len >= TH4 -> 4 rows/CTA, else 8

// Scratch: x-projections (gate 256 cols, cand 128 cols) per (b,t). ~402MB static.
__device__ float g_xproj[(size_t)B_ * T_ * GC];
__device__ int   g_order[B_];
__device__ int4  g_groups[B_ / 4 + 8];   // {pos, bucket, nrows, maxlen}
__device__ int   g_ngroups;

// ---------------- packed f32x2 helpers (sm_103a) ----------------
typedef unsigned long long f32x2;
__device__ __forceinline__ float2 unpack2(f32x2 v) {
    float2 f; asm("mov.b64 {%0,%1}, %2;" : "=f"(f.x), "=f"(f.y) : "l"(v)); return f;
}
__device__ __forceinline__ f32x2 fma2(f32x2 a, f32x2 b, f32x2 c) {
    f32x2 d; asm("fma.rn.f32x2 %0, %1, %2, %3;" : "=l"(d) : "l"(a), "l"(b), "l"(c)); return d;
}
__device__ __forceinline__ float hsum2(f32x2 v) {
    float2 f = unpack2(v); return f.x + f.y;
}

__device__ __forceinline__ float sigmoidf_(float x) {
    return __fdividef(1.0f, 1.0f + __expf(-x));
}
__device__ __forceinline__ float tanhf_(float x) {
    return 1.0f - __fdividef(2.0f, __expf(2.0f * x) + 1.0f);
}

// ---------------- counting sort (desc by len) + load-balanced grouping ----------------
__global__ void sort_group_kernel(const int* __restrict__ seq_lens) {
    __shared__ int hist[T_];
    __shared__ int offs[T_];
    __shared__ int slens[B_];
    int tid = threadIdx.x;
    for (int i = tid; i < T_; i += 256) hist[i] = 0;
    __syncthreads();
    for (int i = tid; i < B_; i += 256) {
        int key = T_ - 1 - seq_lens[i];
        atomicAdd(&hist[key], 1);
    }
    __syncthreads();
    if (tid == 0) {
        int s = 0;
        for (int k = 0; k < T_; k++) { offs[k] = s; s += hist[k]; }
    }
    __syncthreads();
    for (int i = tid; i < T_; i += 256) hist[i] = 0;
    __syncthreads();
    for (int i = tid; i < B_; i += 256) {
        int key = T_ - 1 - seq_lens[i];
        int pos = offs[key] + atomicAdd(&hist[key], 1);
        g_order[pos] = i;
    }
    __syncthreads();
    for (int i = tid; i < B_; i += 256) slens[i] = seq_lens[g_order[i]];
    __syncthreads();
    if (tid == 0) {
        int pos = 0, g = 0;
        while (pos < B_) {
            int L = slens[pos];
            int R = (L >= TH4) ? 4 : 8;
            int nr = min(R, B_ - pos);
            g_groups[g] = make_int4(pos, R, nr, L);
            pos += nr; g++;
        }
        g_ngroups = g;
    }
}

// ---------------- Phase A: xproj[b,t,:] = emb[item[b,t]] @ [Wgx|Wcx] + [gb|cb] --------
// grid: (b, t-tile of 32) = 8192 blocks, 256 threads, ~110KB smem -> 2 CTAs/SM.
// Weights transposed [col][k] stride AWS; k-pair packed fma2 (81% FMA density).
__global__ void __launch_bounds__(256, 2) xproj_kernel(
    const int*   __restrict__ item_his,
    const int*   __restrict__ seq_lens,
    const float* __restrict__ emb,
    const float* __restrict__ gk, const float* __restrict__ gb,
    const float* __restrict__ ck, const float* __restrict__ cb)
{
    extern __shared__ float smem[];
    float* sWt = smem;              // [384][AWS]
    float* sX  = sWt + GC * AWS;    // [32][64] row-major

    int b  = blockIdx.x >> 3;
    int t0 = (blockIdx.x & 7) << 5;
    int len = seq_lens[b];
    if (t0 >= len) return;

    int tid = threadIdx.x;
    int j   = tid & 127;
    int rh  = tid >> 7;   // row-half: 0 -> rows 0..15, 1 -> rows 16..31

    // weights transposed: sWt[col][k] = Wx[k][col]; global reads coalesced over col
    for (int i = tid; i < 64 * GC; i += 256) {
        int k = i / GC, col = i - k * GC;
        sWt[col * AWS + k] = (col < 256) ? gk[k * 256 + col] : ck[k * 128 + (col - 256)];
    }

    // gather 32 embedding rows into sX[r][k]
    {
        int r  = tid >> 3;
        int c8 = tid & 7;
        int item = item_his[b * T_ + t0 + r];
        const float4* erow = reinterpret_cast<const float4*>(emb + (size_t)item * D_ + c8 * 8);
        float4 v0 = erow[0], v1 = erow[1];
        *reinterpret_cast<float4*>(&sX[r * 64 + c8 * 8])     = v0;
        *reinterpret_cast<float4*>(&sX[r * 64 + c8 * 8 + 4]) = v1;
    }
    __syncthreads();

    float bias0 = gb[j], bias1 = gb[128 + j], bias2 = cb[j];
    const float* w0 = sWt + j * AWS;
    const float* w1 = sWt + (j + 128) * AWS;
    const float* w2 = sWt + (j + 256) * AWS;

    #pragma unroll
    for (int pass = 0; pass < 2; pass++) {
        int r0 = rh * 16 + pass * 8;
        f32x2 acc[3][8];
        #pragma unroll
        for (int c = 0; c < 3; c++)
            #pragma unroll
            for (int r = 0; r < 8; r++) acc[c][r] = 0ull;

        #pragma unroll 4
        for (int kk = 0; kk < 16; kk++) {          // 4 k per iter, k-pair packed
            ulonglong2 wa = *reinterpret_cast<const ulonglong2*>(w0 + kk * 4);
            ulonglong2 wb = *reinterpret_cast<const ulonglong2*>(w1 + kk * 4);
            ulonglong2 wc = *reinterpret_cast<const ulonglong2*>(w2 + kk * 4);
            #pragma unroll
            for (int r = 0; r < 8; r++) {
                ulonglong2 x = *reinterpret_cast<const ulonglong2*>(&sX[(r0 + r) * 64 + kk * 4]);
                acc[0][r] = fma2(x.x, wa.x, acc[0][r]);
                acc[0][r] = fma2(x.y, wa.y, acc[0][r]);
                acc[1][r] = fma2(x.x, wb.x, acc[1][r]);
                acc[1][r] = fma2(x.y, wb.y, acc[1][r]);
                acc[2][r] = fma2(x.x, wc.x, acc[2][r]);
                acc[2][r] = fma2(x.y, wc.y, acc[2][r]);
            }
        }

        #pragma unroll
        for (int r = 0; r < 8; r++) {
            float* orow = g_xproj + ((size_t)b * T_ + t0 + r0 + r) * GC;
            orow[j]       = hsum2(acc[0][r]) + bias0;
            orow[128 + j] = hsum2(acc[1][r]) + bias1;
            orow[256 + j] = hsum2(acc[2][r]) + bias2;
        }
    }
}

// ---------------- Phase B: sequential GRU, R in {4,8} rows/CTA, 256 threads -----------
template<int R>
__device__ __forceinline__ void gru_run(
    const float* __restrict__ sWt, float* __restrict__ ht, float* __restrict__ rt,
    float* __restrict__ pc, const int* __restrict__ srow, const int* __restrict__ slen,
    int nr, int maxlen, float* __restrict__ out)
{
    int tid = threadIdx.x;
    int j   = tid & 127;
    bool hi = tid >= 128;   // warps 0-3 lo, 4-7 hi

    const float* xb[R];
    int len_[R];
    #pragma unroll
    for (int r = 0; r < R; r++) {
        int row = (r < nr) ? srow[r] : 0;
        len_[r] = slen[r];
        xb[r]   = g_xproj + (size_t)row * (T_ * GC);
    }

    const float* wg = sWt + tid * WS;
    const float* wc = sWt + (256 + j) * WS + (hi ? 64 : 0);

    float u_[R];

    for (int t = 0; t < maxlen; t++) {
        float px0[R], px1[R];
        #pragma unroll
        for (int r = 0; r < R; r++) {
            px0[r] = 0.0f; px1[r] = 0.0f;
            if (t < len_[r]) {
                const float* xp = xb[r] + (size_t)t * GC;
                if (!hi) { px0[r] = xp[j]; }
                else     { px0[r] = xp[128 + j]; px1[r] = xp[256 + j]; }
            }
        }

        // gate GEMM: col tid, R rows, k-pair packed
        f32x2 acc[R];
        #pragma unroll
        for (int r = 0; r < R; r++) acc[r] = 0ull;
        #pragma unroll 4
        for (int kk = 0; kk < 32; kk++) {
            ulonglong2 w = *reinterpret_cast<const ulonglong2*>(wg + kk * 4);
            #pragma unroll
            for (int r = 0; r < R; r++) {
                ulonglong2 h = *reinterpret_cast<const ulonglong2*>(ht + r * 128 + kk * 4);
                acc[r] = fma2(h.x, w.x, acc[r]);
                acc[r] = fma2(h.y, w.y, acc[r]);
            }
        }

        #pragma unroll
        for (int r = 0; r < R; r++) {
            float s = sigmoidf_(hsum2(acc[r]) + px0[r]);
            if (!hi) rt[r * 128 + j] = s * ht[r * 128 + j];
            else     u_[r] = s;
        }
        __syncthreads();

        // cand GEMM: col j, k-split halves
        f32x2 cacc[R];
        #pragma unroll
        for (int r = 0; r < R; r++) cacc[r] = 0ull;
        const float* rbase = rt + (hi ? 64 : 0);
        #pragma unroll 4
        for (int kk = 0; kk < 16; kk++) {
            ulonglong2 w = *reinterpret_cast<const ulonglong2*>(wc + kk * 4);
            #pragma unroll
            for (int r = 0; r < R; r++) {
                ulonglong2 h = *reinterpret_cast<const ulonglong2*>(rbase + r * 128 + kk * 4);
                cacc[r] = fma2(h.x, w.x, cacc[r]);
                cacc[r] = fma2(h.y, w.y, cacc[r]);
            }
        }
        if (!hi) {
            #pragma unroll
            for (int r = 0; r < R; r++) pc[r * 128 + j] = hsum2(cacc[r]);
        }
        __syncthreads();

        if (hi) {
            #pragma unroll
            for (int r = 0; r < R; r++) {
                if (t < len_[r]) {
                    float c = tanhf_(hsum2(cacc[r]) + pc[r * 128 + j] + px1[r]);
                    float hold = ht[r * 128 + j];
                    ht[r * 128 + j] = u_[r] * hold + (1.0f - u_[r]) * c;
                }
            }
        }
        __syncthreads();
    }

    if (!hi) {
        #pragma unroll
        for (int r = 0; r < R; r++)
            if (r < nr) out[(size_t)srow[r] * H_ + j] = ht[r * 128 + j];
    }
}

__global__ void __launch_bounds__(256, 1) gru_kernel2(
    const int*   __restrict__ seq_lens,
    const float* __restrict__ gk,
    const float* __restrict__ ck,
    float*       __restrict__ out)
{
    extern __shared__ float smem[];
    float* sWt = smem;                    // [384][WS]
    float* ht  = sWt + GC * WS;           // [RMAX][128]
    float* rt  = ht + RMAX * 128;
    float* pc  = rt + RMAX * 128;
    int*   srow = (int*)(pc + RMAX * 128);
    int*   slen = srow + RMAX;

    int bid = blockIdx.x;
    if (bid >= g_ngroups) return;
    int4 grp = g_groups[bid];
    int tid = threadIdx.x;

    for (int i = tid; i < GC * H_; i += 256) {
        int k = i / GC, col = i - k * GC;
        sWt[col * WS + k] = (col < 256) ? gk[(64 + k) * 256 + col]
                                        : ck[(64 + k) * 128 + (col - 256)];
    }
    for (int i = tid; i < RMAX * 128; i += 256) { ht[i] = 0.0f; rt[i] = 0.0f; pc[i] = 0.0f; }
    if (tid < RMAX) {
        int r = tid;
        int row = (r < grp.z) ? g_order[grp.x + r] : 0;
        srow[r] = row;
        slen[r] = (r < grp.z) ? seq_lens[row] : 0;
    }
    __syncthreads();

    if (grp.y == 4) gru_run<4>(sWt, ht, rt, pc, srow, slen, grp.z, grp.w, out);
    else            gru_run<8>(sWt, ht, rt, pc, srow, slen, grp.z, grp.w, out);
}

// ---------------- launch ----------------
static const int A_SMEM = (GC * AWS + 32 * 64) * 4;                       // 112640 B
static const int B_SMEM = (GC * WS + 3 * RMAX * 128) * 4 + 2 * RMAX * 4;  // 215104 B

extern "C" void kernel_launch(void* const* d_in, const int* in_sizes, int n_in,
                              void* d_out, int out_size) {
    const int*   item_his = (const int*)  d_in[0];
    const int*   seq_lens = (const int*)  d_in[1];
    const float* emb      = (const float*)d_in[2];
    const float* gk       = (const float*)d_in[3];
    const float* gb       = (const float*)d_in[4];
    const float* ck       = (const float*)d_in[5];
    const float* cb       = (const float*)d_in[6];
    float*       out      = (float*)d_out;

    cudaFuncSetAttribute(xproj_kernel, cudaFuncAttributeMaxDynamicSharedMemorySize, A_SMEM);
    cudaFuncSetAttribute(gru_kernel2,  cudaFuncAttributeMaxDynamicSharedMemorySize, B_SMEM);

    sort_group_kernel<<<1, 256>>>(seq_lens);
    xproj_kernel<<<B_ * (T_ / 32), 256, A_SMEM>>>(item_his, seq_lens, emb, gk, gb, ck, cb);
    gru_kernel2<<<B_ / 4, 256, B_SMEM>>>(seq_lens, gk, ck, out);
}

// round 4
// speedup vs baseline: 1.1858x; 1.0006x over previous
#include <cuda_runtime.h>

#define B_    1024
#define T_    256
#define D_    64
#define H_    128
#define GC    384   // 2H gate cols + H cand cols
#define WS    132   // padded k-stride (gru weights), conflict-free LDS.128
#define AWS   68    // padded k-stride (xproj weights, K=64)
#define RMAX  8
#define TH4   170   // len >= TH4 -> 4 rows/CTA, else 8

// Scratch: x-projections (gate 256 cols, cand 128 cols) per (b,t). ~402MB static.
__device__ float g_xproj[(size_t)B_ * T_ * GC];
__device__ int   g_order[B_];
__device__ int4  g_groups[B_ / 4 + 8];   // {pos, bucket, nrows, maxlen}
__device__ int   g_ngroups;

// ---------------- packed f32x2 helpers (sm_103a) ----------------
typedef unsigned long long f32x2;
__device__ __forceinline__ float2 unpack2(f32x2 v) {
    float2 f; asm("mov.b64 {%0,%1}, %2;" : "=f"(f.x), "=f"(f.y) : "l"(v)); return f;
}
__device__ __forceinline__ f32x2 fma2(f32x2 a, f32x2 b, f32x2 c) {
    f32x2 d; asm("fma.rn.f32x2 %0, %1, %2, %3;" : "=l"(d) : "l"(a), "l"(b), "l"(c)); return d;
}
__device__ __forceinline__ float hsum2(f32x2 v) {
    float2 f = unpack2(v); return f.x + f.y;
}

__device__ __forceinline__ float sigmoidf_(float x) {
    return __fdividef(1.0f, 1.0f + __expf(-x));
}
__device__ __forceinline__ float tanhf_(float x) {
    return 1.0f - __fdividef(2.0f, __expf(2.0f * x) + 1.0f);
}

// ---------------- counting sort (desc by len) + load-balanced grouping ----------------
__global__ void sort_group_kernel(const int* __restrict__ seq_lens) {
    __shared__ int hist[T_];
    __shared__ int offs[T_];
    __shared__ int slens[B_];
    int tid = threadIdx.x;
    for (int i = tid; i < T_; i += 256) hist[i] = 0;
    __syncthreads();
    for (int i = tid; i < B_; i += 256) {
        int key = T_ - 1 - seq_lens[i];
        atomicAdd(&hist[key], 1);
    }
    __syncthreads();
    if (tid == 0) {
        int s = 0;
        for (int k = 0; k < T_; k++) { offs[k] = s; s += hist[k]; }
    }
    __syncthreads();
    for (int i = tid; i < T_; i += 256) hist[i] = 0;
    __syncthreads();
    for (int i = tid; i < B_; i += 256) {
        int key = T_ - 1 - seq_lens[i];
        int pos = offs[key] + atomicAdd(&hist[key], 1);
        g_order[pos] = i;
    }
    __syncthreads();
    for (int i = tid; i < B_; i += 256) slens[i] = seq_lens[g_order[i]];
    __syncthreads();
    if (tid == 0) {
        int pos = 0, g = 0;
        while (pos < B_) {
            int L = slens[pos];
            int R = (L >= TH4) ? 4 : 8;
            int nr = min(R, B_ - pos);
            g_groups[g] = make_int4(pos, R, nr, L);
            pos += nr; g++;
        }
        g_ngroups = g;
    }
}

// ---------------- Phase A: xproj[b,t,:] = emb[item[b,t]] @ [Wgx|Wcx] + [gb|cb] --------
// grid: (b, t-tile of 32) = 8192 blocks, 256 threads, ~110KB smem -> 2 CTAs/SM.
// Weights transposed [col][k] stride AWS; k-pair packed fma2 (81% FMA density).
__global__ void __launch_bounds__(256, 2) xproj_kernel(
    const int*   __restrict__ item_his,
    const int*   __restrict__ seq_lens,
    const float* __restrict__ emb,
    const float* __restrict__ gk, const float* __restrict__ gb,
    const float* __restrict__ ck, const float* __restrict__ cb)
{
    extern __shared__ float smem[];
    float* sWt = smem;              // [384][AWS]
    float* sX  = sWt + GC * AWS;    // [32][64] row-major

    int b  = blockIdx.x >> 3;
    int t0 = (blockIdx.x & 7) << 5;
    int len = seq_lens[b];
    if (t0 >= len) return;

    int tid = threadIdx.x;
    int j   = tid & 127;
    int rh  = tid >> 7;   // row-half: 0 -> rows 0..15, 1 -> rows 16..31

    // weights transposed: sWt[col][k] = Wx[k][col]; global reads coalesced over col
    for (int i = tid; i < 64 * GC; i += 256) {
        int k = i / GC, col = i - k * GC;
        sWt[col * AWS + k] = (col < 256) ? gk[k * 256 + col] : ck[k * 128 + (col - 256)];
    }

    // gather 32 embedding rows into sX[r][k]
    {
        int r  = tid >> 3;
        int c8 = tid & 7;
        int item = item_his[b * T_ + t0 + r];
        const float4* erow = reinterpret_cast<const float4*>(emb + (size_t)item * D_ + c8 * 8);
        float4 v0 = erow[0], v1 = erow[1];
        *reinterpret_cast<float4*>(&sX[r * 64 + c8 * 8])     = v0;
        *reinterpret_cast<float4*>(&sX[r * 64 + c8 * 8 + 4]) = v1;
    }
    __syncthreads();

    float bias0 = gb[j], bias1 = gb[128 + j], bias2 = cb[j];
    const float* w0 = sWt + j * AWS;
    const float* w1 = sWt + (j + 128) * AWS;
    const float* w2 = sWt + (j + 256) * AWS;

    #pragma unroll
    for (int pass = 0; pass < 2; pass++) {
        int r0 = rh * 16 + pass * 8;
        f32x2 acc[3][8];
        #pragma unroll
        for (int c = 0; c < 3; c++)
            #pragma unroll
            for (int r = 0; r < 8; r++) acc[c][r] = 0ull;

        #pragma unroll 4
        for (int kk = 0; kk < 16; kk++) {          // 4 k per iter, k-pair packed
            ulonglong2 wa = *reinterpret_cast<const ulonglong2*>(w0 + kk * 4);
            ulonglong2 wb = *reinterpret_cast<const ulonglong2*>(w1 + kk * 4);
            ulonglong2 wc = *reinterpret_cast<const ulonglong2*>(w2 + kk * 4);
            #pragma unroll
            for (int r = 0; r < 8; r++) {
                ulonglong2 x = *reinterpret_cast<const ulonglong2*>(&sX[(r0 + r) * 64 + kk * 4]);
                acc[0][r] = fma2(x.x, wa.x, acc[0][r]);
                acc[0][r] = fma2(x.y, wa.y, acc[0][r]);
                acc[1][r] = fma2(x.x, wb.x, acc[1][r]);
                acc[1][r] = fma2(x.y, wb.y, acc[1][r]);
                acc[2][r] = fma2(x.x, wc.x, acc[2][r]);
                acc[2][r] = fma2(x.y, wc.y, acc[2][r]);
            }
        }

        #pragma unroll
        for (int r = 0; r < 8; r++) {
            float* orow = g_xproj + ((size_t)b * T_ + t0 + r0 + r) * GC;
            orow[j]       = hsum2(acc[0][r]) + bias0;
            orow[128 + j] = hsum2(acc[1][r]) + bias1;
            orow[256 + j] = hsum2(acc[2][r]) + bias2;
        }
    }
}

// ---------------- Phase B: sequential GRU, R in {4,8} rows/CTA, 256 threads -----------
template<int R>
__device__ __forceinline__ void gru_run(
    const float* __restrict__ sWt, float* __restrict__ ht, float* __restrict__ rt,
    float* __restrict__ pc, const int* __restrict__ srow, const int* __restrict__ slen,
    int nr, int maxlen, float* __restrict__ out)
{
    int tid = threadIdx.x;
    int j   = tid & 127;
    bool hi = tid >= 128;   // warps 0-3 lo, 4-7 hi

    const float* xb[R];
    int len_[R];
    #pragma unroll
    for (int r = 0; r < R; r++) {
        int row = (r < nr) ? srow[r] : 0;
        len_[r] = slen[r];
        xb[r]   = g_xproj + (size_t)row * (T_ * GC);
    }

    const float* wg = sWt + tid * WS;
    const float* wc = sWt + (256 + j) * WS + (hi ? 64 : 0);

    float u_[R];

    for (int t = 0; t < maxlen; t++) {
        float px0[R], px1[R];
        #pragma unroll
        for (int r = 0; r < R; r++) {
            px0[r] = 0.0f; px1[r] = 0.0f;
            if (t < len_[r]) {
                const float* xp = xb[r] + (size_t)t * GC;
                if (!hi) { px0[r] = xp[j]; }
                else     { px0[r] = xp[128 + j]; px1[r] = xp[256 + j]; }
            }
        }

        // gate GEMM: col tid, R rows, k-pair packed
        f32x2 acc[R];
        #pragma unroll
        for (int r = 0; r < R; r++) acc[r] = 0ull;
        #pragma unroll 4
        for (int kk = 0; kk < 32; kk++) {
            ulonglong2 w = *reinterpret_cast<const ulonglong2*>(wg + kk * 4);
            #pragma unroll
            for (int r = 0; r < R; r++) {
                ulonglong2 h = *reinterpret_cast<const ulonglong2*>(ht + r * 128 + kk * 4);
                acc[r] = fma2(h.x, w.x, acc[r]);
                acc[r] = fma2(h.y, w.y, acc[r]);
            }
        }

        #pragma unroll
        for (int r = 0; r < R; r++) {
            float s = sigmoidf_(hsum2(acc[r]) + px0[r]);
            if (!hi) rt[r * 128 + j] = s * ht[r * 128 + j];
            else     u_[r] = s;
        }
        __syncthreads();

        // cand GEMM: col j, k-split halves
        f32x2 cacc[R];
        #pragma unroll
        for (int r = 0; r < R; r++) cacc[r] = 0ull;
        const float* rbase = rt + (hi ? 64 : 0);
        #pragma unroll 4
        for (int kk = 0; kk < 16; kk++) {
            ulonglong2 w = *reinterpret_cast<const ulonglong2*>(wc + kk * 4);
            #pragma unroll
            for (int r = 0; r < R; r++) {
                ulonglong2 h = *reinterpret_cast<const ulonglong2*>(rbase + r * 128 + kk * 4);
                cacc[r] = fma2(h.x, w.x, cacc[r]);
                cacc[r] = fma2(h.y, w.y, cacc[r]);
            }
        }
        if (!hi) {
            #pragma unroll
            for (int r = 0; r < R; r++) pc[r * 128 + j] = hsum2(cacc[r]);
        }
        __syncthreads();

        if (hi) {
            #pragma unroll
            for (int r = 0; r < R; r++) {
                if (t < len_[r]) {
                    float c = tanhf_(hsum2(cacc[r]) + pc[r * 128 + j] + px1[r]);
                    float hold = ht[r * 128 + j];
                    ht[r * 128 + j] = u_[r] * hold + (1.0f - u_[r]) * c;
                }
            }
        }
        __syncthreads();
    }

    if (!hi) {
        #pragma unroll
        for (int r = 0; r < R; r++)
            if (r < nr) out[(size_t)srow[r] * H_ + j] = ht[r * 128 + j];
    }
}

__global__ void __launch_bounds__(256, 1) gru_kernel2(
    const int*   __restrict__ seq_lens,
    const float* __restrict__ gk,
    const float* __restrict__ ck,
    float*       __restrict__ out)
{
    extern __shared__ float smem[];
    float* sWt = smem;                    // [384][WS]
    float* ht  = sWt + GC * WS;           // [RMAX][128]
    float* rt  = ht + RMAX * 128;
    float* pc  = rt + RMAX * 128;
    int*   srow = (int*)(pc + RMAX * 128);
    int*   slen = srow + RMAX;

    int bid = blockIdx.x;
    if (bid >= g_ngroups) return;
    int4 grp = g_groups[bid];
    int tid = threadIdx.x;

    for (int i = tid; i < GC * H_; i += 256) {
        int k = i / GC, col = i - k * GC;
        sWt[col * WS + k] = (col < 256) ? gk[(64 + k) * 256 + col]
                                        : ck[(64 + k) * 128 + (col - 256)];
    }
    for (int i = tid; i < RMAX * 128; i += 256) { ht[i] = 0.0f; rt[i] = 0.0f; pc[i] = 0.0f; }
    if (tid < RMAX) {
        int r = tid;
        int row = (r < grp.z) ? g_order[grp.x + r] : 0;
        srow[r] = row;
        slen[r] = (r < grp.z) ? seq_lens[row] : 0;
    }
    __syncthreads();

    if (grp.y == 4) gru_run<4>(sWt, ht, rt, pc, srow, slen, grp.z, grp.w, out);
    else            gru_run<8>(sWt, ht, rt, pc, srow, slen, grp.z, grp.w, out);
}

// ---------------- launch ----------------
static const int A_SMEM = (GC * AWS + 32 * 64) * 4;                       // 112640 B
static const int B_SMEM = (GC * WS + 3 * RMAX * 128) * 4 + 2 * RMAX * 4;  // 215104 B

extern "C" void kernel_launch(void* const* d_in, const int* in_sizes, int n_in,
                              void* d_out, int out_size) {
    const int*   item_his = (const int*)  d_in[0];
    const int*   seq_lens = (const int*)  d_in[1];
    const float* emb      = (const float*)d_in[2];
    const float* gk       = (const float*)d_in[3];
    const float* gb       = (const float*)d_in[4];
    const float* ck       = (const float*)d_in[5];
    const float* cb       = (const float*)d_in[6];
    float*       out      = (float*)d_out;

    cudaFuncSetAttribute(xproj_kernel, cudaFuncAttributeMaxDynamicSharedMemorySize, A_SMEM);
    cudaFuncSetAttribute(gru_kernel2,  cudaFuncAttributeMaxDynamicSharedMemorySize, B_SMEM);

    sort_group_kernel<<<1, 256>>>(seq_lens);
    xproj_kernel<<<B_ * (T_ / 32), 256, A_SMEM>>>(item_his, seq_lens, emb, gk, gb, ck, cb);
    gru_kernel2<<<B_ / 4, 256, B_SMEM>>>(seq_lens, gk, ck, out);
}

// round 7
// speedup vs baseline: 1.2474x; 1.0519x over previous
#include <cuda_runtime.h>
#include <cuda_bf16.h>
#include <cstdint>

#define B_    1024
#define T_    256
#define D_    64
#define H_    128
#define GC    384
#define RMAX  8
#define TH_R4 170   // len >= TH_R4 -> 4 rows/CTA, else 8

__device__ float g_xproj[(size_t)B_ * T_ * GC];
__device__ int   g_order[B_];
__device__ int4  g_groups[B_ / 4 + 8];
__device__ int   g_ngroups;

// ---------------- packed f32x2 helpers ----------------
typedef unsigned long long f32x2;
__device__ __forceinline__ f32x2 pack2(float lo, float hi) {
    f32x2 r; asm("mov.b64 %0, {%1,%2};" : "=l"(r) : "f"(lo), "f"(hi)); return r;
}
__device__ __forceinline__ float hsum2(f32x2 v) {
    float x, y; asm("mov.b64 {%0,%1}, %2;" : "=f"(x), "=f"(y) : "l"(v)); return x + y;
}
__device__ __forceinline__ f32x2 fma2(f32x2 a, f32x2 b, f32x2 c) {
    f32x2 d; asm("fma.rn.f32x2 %0, %1, %2, %3;" : "=l"(d) : "l"(a), "l"(b), "l"(c)); return d;
}
__device__ __forceinline__ float sigmoidf_(float x) {
    return __fdividef(1.0f, 1.0f + __expf(-x));
}
__device__ __forceinline__ float tanhf_(float x) {
    return 1.0f - __fdividef(2.0f, __expf(2.0f * x) + 1.0f);
}

// ---------------- warp-level bf16 MMA (PTX baseline, sm_80+) ----------------
__device__ __forceinline__ void mma16816(float* d, const uint32_t* a, const uint32_t* b) {
    asm volatile(
        "mma.sync.aligned.m16n8k16.row.col.f32.bf16.bf16.f32 "
        "{%0,%1,%2,%3}, {%4,%5,%6,%7}, {%8,%9}, {%0,%1,%2,%3};"
        : "+f"(d[0]), "+f"(d[1]), "+f"(d[2]), "+f"(d[3])
        : "r"(a[0]), "r"(a[1]), "r"(a[2]), "r"(a[3]), "r"(b[0]), "r"(b[1]));
}

// ---------------- Phase A: split-bf16 mma.sync GEMM ----------------
// Per CTA: 128 (b,t) rows x 384 cols, K=64. 256 threads (8 warps), warp w -> m-tile w.
// smem byte offsets (stride 72 bf16 rows -> conflict-free frag LDS.32)
static constexpr int BIAS_OFF = 0;        // 384 f32
static constexpr int AH_OFF   = 1536;     // [128][72] bf16
static constexpr int AL_OFF   = 19968;
static constexpr int BH_OFF   = 38400;    // [384][72] bf16 (transposed: [n][k])
static constexpr int BL_OFF   = 93696;
static constexpr int PA_SMEM  = 148992;
#define SA 72

__global__ void __launch_bounds__(256, 1) xproj_mma_kernel(
    const int* __restrict__ item_his, const int* __restrict__ seq_lens,
    const float* __restrict__ emb,
    const float* __restrict__ gk, const float* __restrict__ gb,
    const float* __restrict__ ck, const float* __restrict__ cb)
{
    extern __shared__ char dynsmem[];
    float*         sBias = (float*)(dynsmem + BIAS_OFF);
    __nv_bfloat16* sAh   = (__nv_bfloat16*)(dynsmem + AH_OFF);
    __nv_bfloat16* sAl   = (__nv_bfloat16*)(dynsmem + AL_OFF);
    __nv_bfloat16* sBh   = (__nv_bfloat16*)(dynsmem + BH_OFF);
    __nv_bfloat16* sBl   = (__nv_bfloat16*)(dynsmem + BL_OFF);

    int b  = blockIdx.x >> 1;
    int t0 = (blockIdx.x & 1) << 7;
    if (t0 >= seq_lens[b]) return;

    int tid = threadIdx.x;

    for (int i = tid; i < GC; i += 256) sBias[i] = (i < 256) ? gb[i] : cb[i - 256];

    // A gather: 2 threads per row, each 32 cols; split bf16 hi/lo
    {
        int r = tid >> 1, half = tid & 1;
        int item = item_his[b * T_ + t0 + r];
        const float4* e4 = reinterpret_cast<const float4*>(emb + (size_t)item * D_ + half * 32);
        #pragma unroll
        for (int q = 0; q < 8; q++) {
            float4 v = e4[q];
            float f[4] = {v.x, v.y, v.z, v.w};
            int c0 = half * 32 + q * 4;
            #pragma unroll
            for (int i = 0; i < 2; i++) {
                __nv_bfloat162 hv, lv;
                hv.x = __float2bfloat16(f[2*i]);
                hv.y = __float2bfloat16(f[2*i+1]);
                lv.x = __float2bfloat16(f[2*i]   - __bfloat162float(hv.x));
                lv.y = __float2bfloat16(f[2*i+1] - __bfloat162float(hv.y));
                *reinterpret_cast<__nv_bfloat162*>(&sAh[r * SA + c0 + 2*i]) = hv;
                *reinterpret_cast<__nv_bfloat162*>(&sAl[r * SA + c0 + 2*i]) = lv;
            }
        }
    }
    // B transposed fill: sB[n][k] = Wx[k][n]
    for (int idx = tid; idx < D_ * GC; idx += 256) {
        int k = idx / GC, n = idx - k * GC;
        float w = (n < 256) ? gk[k * 256 + n] : ck[k * 128 + (n - 256)];
        __nv_bfloat16 h = __float2bfloat16(w);
        sBh[n * SA + k] = h;
        sBl[n * SA + k] = __float2bfloat16(w - __bfloat162float(h));
    }
    __syncthreads();

    int wid = tid >> 5, lane = tid & 31;
    int gid = lane >> 2, tig = lane & 3;
    int m0 = wid * 16;

    // register-cache A fragments for this warp's m-tile: 4 k-steps x (hi,lo)
    uint32_t ah[4][4], al[4][4];
    #pragma unroll
    for (int ks = 0; ks < 4; ks++) {
        int c = ks * 16 + 2 * tig;
        ah[ks][0] = *reinterpret_cast<const uint32_t*>(&sAh[(m0+gid)   * SA + c]);
        ah[ks][1] = *reinterpret_cast<const uint32_t*>(&sAh[(m0+gid+8) * SA + c]);
        ah[ks][2] = *reinterpret_cast<const uint32_t*>(&sAh[(m0+gid)   * SA + c + 8]);
        ah[ks][3] = *reinterpret_cast<const uint32_t*>(&sAh[(m0+gid+8) * SA + c + 8]);
        al[ks][0] = *reinterpret_cast<const uint32_t*>(&sAl[(m0+gid)   * SA + c]);
        al[ks][1] = *reinterpret_cast<const uint32_t*>(&sAl[(m0+gid+8) * SA + c]);
        al[ks][2] = *reinterpret_cast<const uint32_t*>(&sAl[(m0+gid)   * SA + c + 8]);
        al[ks][3] = *reinterpret_cast<const uint32_t*>(&sAl[(m0+gid+8) * SA + c + 8]);
    }

    float* outbase = g_xproj + ((size_t)b * T_ + t0) * GC;

    // 48 n-tiles, 2 at a time (independent HMMA chains)
    for (int nt = 0; nt < 48; nt += 2) {
        float acc0[4] = {0.f, 0.f, 0.f, 0.f};
        float acc1[4] = {0.f, 0.f, 0.f, 0.f};
        #pragma unroll
        for (int ks = 0; ks < 4; ks++) {
            int c = ks * 16 + 2 * tig;
            uint32_t bh0[2], bl0[2], bh1[2], bl1[2];
            int n0 = (nt * 8 + gid) * SA, n1 = ((nt + 1) * 8 + gid) * SA;
            bh0[0] = *reinterpret_cast<const uint32_t*>(&sBh[n0 + c]);
            bh0[1] = *reinterpret_cast<const uint32_t*>(&sBh[n0 + c + 8]);
            bl0[0] = *reinterpret_cast<const uint32_t*>(&sBl[n0 + c]);
            bl0[1] = *reinterpret_cast<const uint32_t*>(&sBl[n0 + c + 8]);
            bh1[0] = *reinterpret_cast<const uint32_t*>(&sBh[n1 + c]);
            bh1[1] = *reinterpret_cast<const uint32_t*>(&sBh[n1 + c + 8]);
            bl1[0] = *reinterpret_cast<const uint32_t*>(&sBl[n1 + c]);
            bl1[1] = *reinterpret_cast<const uint32_t*>(&sBl[n1 + c + 8]);
            mma16816(acc0, ah[ks], bh0);
            mma16816(acc1, ah[ks], bh1);
            mma16816(acc0, ah[ks], bl0);
            mma16816(acc1, ah[ks], bl1);
            mma16816(acc0, al[ks], bh0);
            mma16816(acc1, al[ks], bh1);
        }
        // epilogue: D[gid][2tig..], D[gid+8][2tig..] for both n-tiles, + bias
        #pragma unroll
        for (int p = 0; p < 2; p++) {
            float* acc = p ? acc1 : acc0;
            int ncol = (nt + p) * 8 + 2 * tig;
            float2 bias = *reinterpret_cast<const float2*>(&sBias[ncol]);
            float2 o0 = {acc[0] + bias.x, acc[1] + bias.y};
            float2 o1 = {acc[2] + bias.x, acc[3] + bias.y};
            *reinterpret_cast<float2*>(outbase + (size_t)(m0 + gid)     * GC + ncol) = o0;
            *reinterpret_cast<float2*>(outbase + (size_t)(m0 + gid + 8) * GC + ncol) = o1;
        }
    }
}

// ---------------- counting sort (desc) + grouping {4,8} ----------------
__global__ void sort_group_kernel(const int* __restrict__ seq_lens) {
    __shared__ int hist[T_];
    __shared__ int offs[T_];
    __shared__ int slens[B_];
    int tid = threadIdx.x;
    for (int i = tid; i < T_; i += 256) hist[i] = 0;
    __syncthreads();
    for (int i = tid; i < B_; i += 256) atomicAdd(&hist[T_ - 1 - seq_lens[i]], 1);
    __syncthreads();
    if (tid == 0) { int s = 0; for (int k = 0; k < T_; k++) { offs[k] = s; s += hist[k]; } }
    __syncthreads();
    for (int i = tid; i < T_; i += 256) hist[i] = 0;
    __syncthreads();
    for (int i = tid; i < B_; i += 256) {
        int key = T_ - 1 - seq_lens[i];
        g_order[offs[key] + atomicAdd(&hist[key], 1)] = i;
    }
    __syncthreads();
    for (int i = tid; i < B_; i += 256) slens[i] = seq_lens[g_order[i]];
    __syncthreads();
    if (tid == 0) {
        int pos = 0, g = 0;
        while (pos < B_) {
            int L = slens[pos];
            int R = (L >= TH_R4) ? 4 : 8;
            int nr = min(R, B_ - pos);
            g_groups[g] = make_int4(pos, R, nr, L);
            pos += nr; g++;
        }
        g_ngroups = g;
    }
}

// ---------------- Phase B: GRU, gate weights register-resident ----------------
template<int R>
__device__ void gru_run(
    const f32x2* __restrict__ wg, const float* __restrict__ sWc,
    float* __restrict__ ht, float* __restrict__ rt, float* __restrict__ pc,
    const int* __restrict__ srow, const int* __restrict__ slen,
    int maxlen, float* __restrict__ out, int nr)
{
    int tid = threadIdx.x, j = tid & 127;
    bool hi = tid >= 128;

    int xoff[R], len_[R];
    #pragma unroll
    for (int r = 0; r < R; r++) {
        len_[r] = slen[r];
        xoff[r] = srow[r] * (T_ * GC);
    }
    const float* wc = sWc + j * 132 + (hi ? 64 : 0);
    float u_[R], cc[R];

    for (int t = 0; t < maxlen; t++) {
        float px1[R];
        if (hi) {
            #pragma unroll
            for (int r = 0; r < R; r++)
                px1[r] = (t < len_[r]) ? g_xproj[xoff[r] + t * GC + 256 + j] : 0.0f;
        }
        // ---- gate GEMM (weights in regs) ----
        float px0[R];
        #pragma unroll
        for (int r = 0; r < R; r++)
            px0[r] = (t < len_[r]) ? g_xproj[xoff[r] + t * GC + tid] : 0.0f;
        f32x2 acc[R];
        #pragma unroll
        for (int r = 0; r < R; r++) acc[r] = 0ull;
        #pragma unroll 4
        for (int kk = 0; kk < 32; kk++) {
            #pragma unroll
            for (int r = 0; r < R; r++) {
                ulonglong2 h = *reinterpret_cast<const ulonglong2*>(ht + r * 128 + kk * 4);
                acc[r] = fma2(h.x, wg[2*kk],   acc[r]);
                acc[r] = fma2(h.y, wg[2*kk+1], acc[r]);
            }
        }
        #pragma unroll
        for (int r = 0; r < R; r++) {
            float s = sigmoidf_(hsum2(acc[r]) + px0[r]);
            if (!hi) rt[r * 128 + j] = s * ht[r * 128 + j];
            else     u_[r] = s;
        }
        __syncthreads();
        // ---- cand GEMM: col j, k-split halves ----
        {
            f32x2 cacc[R];
            #pragma unroll
            for (int r = 0; r < R; r++) cacc[r] = 0ull;
            const float* rb_ = rt + (hi ? 64 : 0);
            #pragma unroll 4
            for (int kk = 0; kk < 16; kk++) {
                ulonglong2 w = *reinterpret_cast<const ulonglong2*>(wc + kk * 4);
                #pragma unroll
                for (int r = 0; r < R; r++) {
                    ulonglong2 h = *reinterpret_cast<const ulonglong2*>(rb_ + r * 128 + kk * 4);
                    cacc[r] = fma2(h.x, w.x, cacc[r]);
                    cacc[r] = fma2(h.y, w.y, cacc[r]);
                }
            }
            #pragma unroll
            for (int r = 0; r < R; r++) {
                float v = hsum2(cacc[r]);
                if (!hi) pc[r * 128 + j] = v;
                else     cc[r] = v;
            }
        }
        __syncthreads();
        // ---- update (hi threads own hidden unit j) ----
        if (hi) {
            #pragma unroll
            for (int r = 0; r < R; r++) {
                if (t < len_[r]) {
                    float c = tanhf_(cc[r] + pc[r * 128 + j] + px1[r]);
                    float h0 = ht[r * 128 + j];
                    ht[r * 128 + j] = u_[r] * h0 + (1.0f - u_[r]) * c;
                }
            }
        }
        __syncthreads();
    }
    if (!hi) {
        #pragma unroll
        for (int r = 0; r < R; r++)
            if (r < nr) out[(size_t)srow[r] * H_ + j] = ht[r * 128 + j];
    }
}

__global__ void __launch_bounds__(256, 1) gru_kernel3(
    const int* __restrict__ seq_lens,
    const float* __restrict__ gk, const float* __restrict__ ck,
    float* __restrict__ out)
{
    extern __shared__ char dynsmem[];
    float* sWc = (float*)dynsmem;            // [128 cols][stride 132]
    float* ht  = sWc + 128 * 132;            // [RMAX][128]
    float* rt  = ht + RMAX * 128;
    float* pc  = rt + RMAX * 128;
    int* srow  = (int*)(pc + RMAX * 128);
    int* slen  = srow + RMAX;

    int bid = blockIdx.x;
    if (bid >= g_ngroups) return;
    int4 grp = g_groups[bid];
    int tid = threadIdx.x;

    // gate weights (col=tid) into 64 f32x2 regs
    f32x2 wg[64];
    #pragma unroll
    for (int kk = 0; kk < 64; kk++)
        wg[kk] = pack2(gk[(64 + 2*kk) * 256 + tid], gk[(64 + 2*kk + 1) * 256 + tid]);

    // cand weights transposed [col][k]
    for (int i = tid; i < 128 * 128; i += 256) {
        int k = i >> 7, col = i & 127;
        sWc[col * 132 + k] = ck[(64 + k) * 128 + col];
    }
    for (int i = tid; i < RMAX * 128; i += 256) { ht[i] = 0.0f; rt[i] = 0.0f; pc[i] = 0.0f; }
    if (tid < RMAX) {
        int r = tid;
        int row = (r < grp.z) ? g_order[grp.x + r] : 0;
        srow[r] = row;
        slen[r] = (r < grp.z) ? seq_lens[row] : 0;
    }
    __syncthreads();

    if (grp.y == 4) gru_run<4>(wg, sWc, ht, rt, pc, srow, slen, grp.w, out, grp.z);
    else            gru_run<8>(wg, sWc, ht, rt, pc, srow, slen, grp.w, out, grp.z);
}

// ---------------- launch ----------------
static const int B_SMEM = 128 * 132 * 4 + 3 * RMAX * 128 * 4 + 2 * RMAX * 4;  // 79936

extern "C" void kernel_launch(void* const* d_in, const int* in_sizes, int n_in,
                              void* d_out, int out_size) {
    const int*   item_his = (const int*)  d_in[0];
    const int*   seq_lens = (const int*)  d_in[1];
    const float* emb      = (const float*)d_in[2];
    const float* gk       = (const float*)d_in[3];
    const float* gb       = (const float*)d_in[4];
    const float* ck       = (const float*)d_in[5];
    const float* cb       = (const float*)d_in[6];
    float*       out      = (float*)d_out;

    cudaFuncSetAttribute(xproj_mma_kernel, cudaFuncAttributeMaxDynamicSharedMemorySize, PA_SMEM);
    cudaFuncSetAttribute(gru_kernel3,      cudaFuncAttributeMaxDynamicSharedMemorySize, B_SMEM);

    xproj_mma_kernel<<<B_ * 2, 256, PA_SMEM>>>(item_his, seq_lens, emb, gk, gb, ck, cb);
    sort_group_kernel<<<1, 256>>>(seq_lens);
    gru_kernel3<<<B_ / 4, 256, B_SMEM>>>(seq_lens, gk, ck, out);
}

// round 8
// speedup vs baseline: 1.2841x; 1.0295x over previous
#include <cuda_runtime.h>
#include <cuda_bf16.h>
#include <cstdint>

#define B_    1024
#define T_    256
#define D_    64
#define H_    128
#define GC    384
#define RMAX  8
#define TH_R4 170   // len >= TH_R4 -> 4 rows/CTA, else 8

__device__ float g_xproj[(size_t)B_ * T_ * GC];
__device__ int   g_order[B_];
__device__ int4  g_groups[B_ / 4 + 8];
__device__ int   g_ngroups;

// ---------------- packed f32x2 helpers ----------------
typedef unsigned long long f32x2;
__device__ __forceinline__ float hsum2(f32x2 v) {
    float x, y; asm("mov.b64 {%0,%1}, %2;" : "=f"(x), "=f"(y) : "l"(v)); return x + y;
}
__device__ __forceinline__ f32x2 fma2(f32x2 a, f32x2 b, f32x2 c) {
    f32x2 d; asm("fma.rn.f32x2 %0, %1, %2, %3;" : "=l"(d) : "l"(a), "l"(b), "l"(c)); return d;
}
__device__ __forceinline__ float sigmoidf_(float x) {
    return __fdividef(1.0f, 1.0f + __expf(-x));
}
__device__ __forceinline__ float tanhf_(float x) {
    return 1.0f - __fdividef(2.0f, __expf(2.0f * x) + 1.0f);
}

// ---------------- warp-level bf16 MMA ----------------
__device__ __forceinline__ void mma16816(float* d, const uint32_t* a, const uint32_t* b) {
    asm volatile(
        "mma.sync.aligned.m16n8k16.row.col.f32.bf16.bf16.f32 "
        "{%0,%1,%2,%3}, {%4,%5,%6,%7}, {%8,%9}, {%0,%1,%2,%3};"
        : "+f"(d[0]), "+f"(d[1]), "+f"(d[2]), "+f"(d[3])
        : "r"(a[0]), "r"(a[1]), "r"(a[2]), "r"(a[3]), "r"(b[0]), "r"(b[1]));
}

// ---------------- Phase A (+fused sort): split-bf16 mma.sync GEMM ----------------
static constexpr int BIAS_OFF = 0;
static constexpr int AH_OFF   = 1536;
static constexpr int AL_OFF   = 19968;
static constexpr int BH_OFF   = 38400;
static constexpr int BL_OFF   = 93696;
static constexpr int PA_SMEM  = 148992;
#define SA 72

__device__ void sort_group_body(const int* __restrict__ seq_lens, char* dynsmem) {
    int* hist  = (int*)dynsmem;            // 256
    int* offs  = hist + T_;                // 256
    int* slens = offs + T_;                // 1024
    int tid = threadIdx.x;
    for (int i = tid; i < T_; i += 256) hist[i] = 0;
    __syncthreads();
    for (int i = tid; i < B_; i += 256) atomicAdd(&hist[T_ - 1 - seq_lens[i]], 1);
    __syncthreads();
    if (tid == 0) { int s = 0; for (int k = 0; k < T_; k++) { offs[k] = s; s += hist[k]; } }
    __syncthreads();
    for (int i = tid; i < T_; i += 256) hist[i] = 0;
    __syncthreads();
    for (int i = tid; i < B_; i += 256) {
        int key = T_ - 1 - seq_lens[i];
        g_order[offs[key] + atomicAdd(&hist[key], 1)] = i;
    }
    __syncthreads();
    for (int i = tid; i < B_; i += 256) slens[i] = seq_lens[g_order[i]];
    __syncthreads();
    if (tid == 0) {
        int pos = 0, g = 0;
        while (pos < B_) {
            int L = slens[pos];
            int R = (L >= TH_R4) ? 4 : 8;
            int nr = min(R, B_ - pos);
            g_groups[g] = make_int4(pos, R, nr, L);
            pos += nr; g++;
        }
        g_ngroups = g;
    }
}

__global__ void __launch_bounds__(256, 1) xproj_mma_kernel(
    const int* __restrict__ item_his, const int* __restrict__ seq_lens,
    const float* __restrict__ emb,
    const float* __restrict__ gk, const float* __restrict__ gb,
    const float* __restrict__ ck, const float* __restrict__ cb)
{
    extern __shared__ char dynsmem[];

    if (blockIdx.x == 2048) { sort_group_body(seq_lens, dynsmem); return; }

    float*         sBias = (float*)(dynsmem + BIAS_OFF);
    __nv_bfloat16* sAh   = (__nv_bfloat16*)(dynsmem + AH_OFF);
    __nv_bfloat16* sAl   = (__nv_bfloat16*)(dynsmem + AL_OFF);
    __nv_bfloat16* sBh   = (__nv_bfloat16*)(dynsmem + BH_OFF);
    __nv_bfloat16* sBl   = (__nv_bfloat16*)(dynsmem + BL_OFF);

    int b  = blockIdx.x >> 1;
    int t0 = (blockIdx.x & 1) << 7;
    if (t0 >= seq_lens[b]) return;

    int tid = threadIdx.x;

    for (int i = tid; i < GC; i += 256) sBias[i] = (i < 256) ? gb[i] : cb[i - 256];

    {
        int r = tid >> 1, half = tid & 1;
        int item = item_his[b * T_ + t0 + r];
        const float4* e4 = reinterpret_cast<const float4*>(emb + (size_t)item * D_ + half * 32);
        #pragma unroll
        for (int q = 0; q < 8; q++) {
            float4 v = e4[q];
            float f[4] = {v.x, v.y, v.z, v.w};
            int c0 = half * 32 + q * 4;
            #pragma unroll
            for (int i = 0; i < 2; i++) {
                __nv_bfloat162 hv, lv;
                hv.x = __float2bfloat16(f[2*i]);
                hv.y = __float2bfloat16(f[2*i+1]);
                lv.x = __float2bfloat16(f[2*i]   - __bfloat162float(hv.x));
                lv.y = __float2bfloat16(f[2*i+1] - __bfloat162float(hv.y));
                *reinterpret_cast<__nv_bfloat162*>(&sAh[r * SA + c0 + 2*i]) = hv;
                *reinterpret_cast<__nv_bfloat162*>(&sAl[r * SA + c0 + 2*i]) = lv;
            }
        }
    }
    for (int idx = tid; idx < D_ * GC; idx += 256) {
        int k = idx / GC, n = idx - k * GC;
        float w = (n < 256) ? gk[k * 256 + n] : ck[k * 128 + (n - 256)];
        __nv_bfloat16 h = __float2bfloat16(w);
        sBh[n * SA + k] = h;
        sBl[n * SA + k] = __float2bfloat16(w - __bfloat162float(h));
    }
    __syncthreads();

    int wid = tid >> 5, lane = tid & 31;
    int gid = lane >> 2, tig = lane & 3;
    int m0 = wid * 16;

    uint32_t ah[4][4], al[4][4];
    #pragma unroll
    for (int ks = 0; ks < 4; ks++) {
        int c = ks * 16 + 2 * tig;
        ah[ks][0] = *reinterpret_cast<const uint32_t*>(&sAh[(m0+gid)   * SA + c]);
        ah[ks][1] = *reinterpret_cast<const uint32_t*>(&sAh[(m0+gid+8) * SA + c]);
        ah[ks][2] = *reinterpret_cast<const uint32_t*>(&sAh[(m0+gid)   * SA + c + 8]);
        ah[ks][3] = *reinterpret_cast<const uint32_t*>(&sAh[(m0+gid+8) * SA + c + 8]);
        al[ks][0] = *reinterpret_cast<const uint32_t*>(&sAl[(m0+gid)   * SA + c]);
        al[ks][1] = *reinterpret_cast<const uint32_t*>(&sAl[(m0+gid+8) * SA + c]);
        al[ks][2] = *reinterpret_cast<const uint32_t*>(&sAl[(m0+gid)   * SA + c + 8]);
        al[ks][3] = *reinterpret_cast<const uint32_t*>(&sAl[(m0+gid+8) * SA + c + 8]);
    }

    float* outbase = g_xproj + ((size_t)b * T_ + t0) * GC;

    for (int nt = 0; nt < 48; nt += 2) {
        float acc0[4] = {0.f, 0.f, 0.f, 0.f};
        float acc1[4] = {0.f, 0.f, 0.f, 0.f};
        #pragma unroll
        for (int ks = 0; ks < 4; ks++) {
            int c = ks * 16 + 2 * tig;
            uint32_t bh0[2], bl0[2], bh1[2], bl1[2];
            int n0 = (nt * 8 + gid) * SA, n1 = ((nt + 1) * 8 + gid) * SA;
            bh0[0] = *reinterpret_cast<const uint32_t*>(&sBh[n0 + c]);
            bh0[1] = *reinterpret_cast<const uint32_t*>(&sBh[n0 + c + 8]);
            bl0[0] = *reinterpret_cast<const uint32_t*>(&sBl[n0 + c]);
            bl0[1] = *reinterpret_cast<const uint32_t*>(&sBl[n0 + c + 8]);
            bh1[0] = *reinterpret_cast<const uint32_t*>(&sBh[n1 + c]);
            bh1[1] = *reinterpret_cast<const uint32_t*>(&sBh[n1 + c + 8]);
            bl1[0] = *reinterpret_cast<const uint32_t*>(&sBl[n1 + c]);
            bl1[1] = *reinterpret_cast<const uint32_t*>(&sBl[n1 + c + 8]);
            mma16816(acc0, ah[ks], bh0);
            mma16816(acc1, ah[ks], bh1);
            mma16816(acc0, ah[ks], bl0);
            mma16816(acc1, ah[ks], bl1);
            mma16816(acc0, al[ks], bh0);
            mma16816(acc1, al[ks], bh1);
        }
        #pragma unroll
        for (int p = 0; p < 2; p++) {
            float* acc = p ? acc1 : acc0;
            int ncol = (nt + p) * 8 + 2 * tig;
            float2 bias = *reinterpret_cast<const float2*>(&sBias[ncol]);
            float2 o0 = {acc[0] + bias.x, acc[1] + bias.y};
            float2 o1 = {acc[2] + bias.x, acc[3] + bias.y};
            *reinterpret_cast<float2*>(outbase + (size_t)(m0 + gid)     * GC + ncol) = o0;
            *reinterpret_cast<float2*>(outbase + (size_t)(m0 + gid + 8) * GC + ncol) = o1;
        }
    }
}

// ---------------- Phase B: 512 threads, k-split GEMMs, zero-spill ----------------
// smem floats: sWg[256*132], sWc[128*132], ht[R*128], rt[R*128], pg[2*R*256] (alias pc4[4][R][128])
#define WS 132
static constexpr int G_SMEM = (256*WS + 128*WS + RMAX*128*2 + 2*RMAX*256) * 4 + 64;

template<int R>
__device__ void gru_steps(
    const float* __restrict__ sWg, const float* __restrict__ sWc,
    float* __restrict__ ht, float* __restrict__ rt, float* __restrict__ pg,
    const int* __restrict__ srow, const int* __restrict__ slen,
    int maxlen, float* __restrict__ out, int nr)
{
    int t_ = threadIdx.x;
    int gcol  = t_ & 255;          // gate column 0..255
    int ghalf = t_ >> 8;           // k-half 0/1
    int ccol  = t_ & 127;          // cand column 0..127
    int cq    = t_ >> 7;           // k-quarter 0..3
    int j     = t_ & 127;
    int role  = t_ >> 7;           // 0: r-combine, 1: u-combine+update, 2,3: idle in combines

    float* pc4 = pg;               // alias: pc4[q][r][128]

    int xoff[R], len_[R];
    #pragma unroll
    for (int r = 0; r < R; r++) { len_[r] = slen[r]; xoff[r] = srow[r] * (T_ * GC); }

    const float* wg = sWg + gcol * WS + ghalf * 64;
    const float* wc = sWc + ccol * WS + cq * 32;

    float u_[R], px1[R];

    for (int t = 0; t < maxlen; t++) {
        // prefetch x-projections for combine phases
        float px0[R];
        if (role == 0) {
            #pragma unroll
            for (int r = 0; r < R; r++)
                px0[r] = (t < len_[r]) ? g_xproj[xoff[r] + t * GC + j] : 0.0f;
        } else if (role == 1) {
            #pragma unroll
            for (int r = 0; r < R; r++) {
                px0[r] = (t < len_[r]) ? g_xproj[xoff[r] + t * GC + 128 + j] : 0.0f;
                px1[r] = (t < len_[r]) ? g_xproj[xoff[r] + t * GC + 256 + j] : 0.0f;
            }
        }

        // ---- gate partial: 64-k half dot for col gcol, R rows ----
        {
            f32x2 acc[R];
            #pragma unroll
            for (int r = 0; r < R; r++) acc[r] = 0ull;
            const float* hb = ht + ghalf * 64;
            #pragma unroll 2
            for (int kk = 0; kk < 16; kk++) {
                ulonglong2 w = *reinterpret_cast<const ulonglong2*>(wg + kk * 4);
                #pragma unroll
                for (int r = 0; r < R; r++) {
                    ulonglong2 h = *reinterpret_cast<const ulonglong2*>(hb + r * 128 + kk * 4);
                    acc[r] = fma2(h.x, w.x, acc[r]);
                    acc[r] = fma2(h.y, w.y, acc[r]);
                }
            }
            #pragma unroll
            for (int r = 0; r < R; r++)
                pg[ghalf * (R * 256) + r * 256 + gcol] = hsum2(acc[r]);
        }
        __syncthreads();

        // ---- gate combine ----
        if (role == 0) {
            #pragma unroll
            for (int r = 0; r < R; r++) {
                float s = sigmoidf_(pg[r * 256 + j] + pg[R * 256 + r * 256 + j] + px0[r]);
                rt[r * 128 + j] = s * ht[r * 128 + j];
            }
        } else if (role == 1) {
            #pragma unroll
            for (int r = 0; r < R; r++)
                u_[r] = sigmoidf_(pg[r * 256 + 128 + j] + pg[R * 256 + r * 256 + 128 + j] + px0[r]);
        }
        __syncthreads();

        // ---- cand partial: 32-k quarter dot for col ccol, R rows ----
        {
            f32x2 cacc[R];
            #pragma unroll
            for (int r = 0; r < R; r++) cacc[r] = 0ull;
            const float* rb = rt + cq * 32;
            #pragma unroll 2
            for (int kk = 0; kk < 8; kk++) {
                ulonglong2 w = *reinterpret_cast<const ulonglong2*>(wc + kk * 4);
                #pragma unroll
                for (int r = 0; r < R; r++) {
                    ulonglong2 h = *reinterpret_cast<const ulonglong2*>(rb + r * 128 + kk * 4);
                    cacc[r] = fma2(h.x, w.x, cacc[r]);
                    cacc[r] = fma2(h.y, w.y, cacc[r]);
                }
            }
            #pragma unroll
            for (int r = 0; r < R; r++)
                pc4[cq * (R * 128) + r * 128 + ccol] = hsum2(cacc[r]);
        }
        __syncthreads();

        // ---- update (role 1 owns hidden unit j) ----
        if (role == 1) {
            #pragma unroll
            for (int r = 0; r < R; r++) {
                if (t < len_[r]) {
                    float pre = pc4[r * 128 + j] + pc4[R * 128 + r * 128 + j]
                              + pc4[2 * R * 128 + r * 128 + j] + pc4[3 * R * 128 + r * 128 + j]
                              + px1[r];
                    float c = tanhf_(pre);
                    float h0 = ht[r * 128 + j];
                    ht[r * 128 + j] = u_[r] * h0 + (1.0f - u_[r]) * c;
                }
            }
        }
        __syncthreads();
    }

    if (role == 0) {
        #pragma unroll
        for (int r = 0; r < R; r++)
            if (r < nr) out[(size_t)srow[r] * H_ + j] = ht[r * 128 + j];
    }
}

__global__ void __launch_bounds__(512, 1) gru_kernel4(
    const int* __restrict__ seq_lens,
    const float* __restrict__ gk, const float* __restrict__ ck,
    float* __restrict__ out)
{
    extern __shared__ char dynsmem[];
    float* sWg = (float*)dynsmem;            // [256][WS]
    float* sWc = sWg + 256 * WS;             // [128][WS]
    float* ht  = sWc + 128 * WS;             // [R][128]
    float* rt  = ht + RMAX * 128;
    float* pg  = rt + RMAX * 128;            // [2][R][256], alias pc4[4][R][128]
    int* srow  = (int*)(pg + 2 * RMAX * 256);
    int* slen  = srow + RMAX;

    int bid = blockIdx.x;
    if (bid >= g_ngroups) return;
    int4 grp = g_groups[bid];
    int tid = threadIdx.x;

    // weights transposed [col][k]: global reads coalesced over col
    for (int idx = tid; idx < 128 * GC; idx += 512) {
        int k = idx / GC, col = idx - k * GC;
        float w = (col < 256) ? gk[(64 + k) * 256 + col] : ck[(64 + k) * 128 + (col - 256)];
        if (col < 256) sWg[col * WS + k] = w;
        else           sWc[(col - 256) * WS + k] = w;
    }
    for (int i = tid; i < RMAX * 128; i += 512) { ht[i] = 0.0f; rt[i] = 0.0f; }
    if (tid < RMAX) {
        int r = tid;
        int row = (r < grp.z) ? g_order[grp.x + r] : 0;
        srow[r] = row;
        slen[r] = (r < grp.z) ? seq_lens[row] : 0;
    }
    __syncthreads();

    if (grp.y == 4) gru_steps<4>(sWg, sWc, ht, rt, pg, srow, slen, grp.w, out, grp.z);
    else            gru_steps<8>(sWg, sWc, ht, rt, pg, srow, slen, grp.w, out, grp.z);
}

// ---------------- launch ----------------
extern "C" void kernel_launch(void* const* d_in, const int* in_sizes, int n_in,
                              void* d_out, int out_size) {
    const int*   item_his = (const int*)  d_in[0];
    const int*   seq_lens = (const int*)  d_in[1];
    const float* emb      = (const float*)d_in[2];
    const float* gk       = (const float*)d_in[3];
    const float* gb       = (const float*)d_in[4];
    const float* ck       = (const float*)d_in[5];
    const float* cb       = (const float*)d_in[6];
    float*       out      = (float*)d_out;

    cudaFuncSetAttribute(xproj_mma_kernel, cudaFuncAttributeMaxDynamicSharedMemorySize, PA_SMEM);
    cudaFuncSetAttribute(gru_kernel4,      cudaFuncAttributeMaxDynamicSharedMemorySize, G_SMEM);

    xproj_mma_kernel<<<2049, 256, PA_SMEM>>>(item_his, seq_lens, emb, gk, gb, ck, cb);
    gru_kernel4<<<B_ / 4, 512, G_SMEM>>>(seq_lens, gk, ck, out);
}

// round 9
// speedup vs baseline: 1.6902x; 1.3162x over previous
#include <cuda_runtime.h>
#include <cuda_bf16.h>
#include <cstdint>

#define B_    1024
#define T_    256
#define D_    64
#define H_    128
#define GC    384

__device__ float g_xproj[(size_t)B_ * T_ * GC];
__device__ int   g_order[B_];

__device__ __forceinline__ float sigmoidf_(float x) {
    return __fdividef(1.0f, 1.0f + __expf(-x));
}
__device__ __forceinline__ float tanhf_(float x) {
    return 1.0f - __fdividef(2.0f, __expf(2.0f * x) + 1.0f);
}

// ---------------- warp-level bf16 MMA ----------------
__device__ __forceinline__ void mma16816(float* d, const uint32_t* a, uint32_t b0, uint32_t b1) {
    asm volatile(
        "mma.sync.aligned.m16n8k16.row.col.f32.bf16.bf16.f32 "
        "{%0,%1,%2,%3}, {%4,%5,%6,%7}, {%8,%9}, {%0,%1,%2,%3};"
        : "+f"(d[0]), "+f"(d[1]), "+f"(d[2]), "+f"(d[3])
        : "r"(a[0]), "r"(a[1]), "r"(a[2]), "r"(a[3]), "r"(b0), "r"(b1));
}

__device__ __forceinline__ uint32_t split_pack(float x, float y, uint32_t& lo) {
    __nv_bfloat16 hx = __float2bfloat16(x), hy = __float2bfloat16(y);
    __nv_bfloat162 hp; hp.x = hx; hp.y = hy;
    __nv_bfloat162 lp;
    lp.x = __float2bfloat16(x - __bfloat162float(hx));
    lp.y = __float2bfloat16(y - __bfloat162float(hy));
    lo = *reinterpret_cast<uint32_t*>(&lp);
    return *reinterpret_cast<uint32_t*>(&hp);
}

// ---------------- Phase A (+fused sort): split-bf16 mma.sync GEMM ----------------
static constexpr int BIAS_OFF = 0;
static constexpr int AH_OFF   = 1536;
static constexpr int AL_OFF   = 19968;
static constexpr int BH_OFF   = 38400;
static constexpr int BL_OFF   = 93696;
static constexpr int PA_SMEM  = 148992;
#define SA 72

__device__ void sort_body(const int* __restrict__ seq_lens, char* dynsmem) {
    int* hist  = (int*)dynsmem;
    int* offs  = hist + T_;
    int tid = threadIdx.x;
    for (int i = tid; i < T_; i += 256) hist[i] = 0;
    __syncthreads();
    for (int i = tid; i < B_; i += 256) atomicAdd(&hist[T_ - 1 - seq_lens[i]], 1);
    __syncthreads();
    if (tid == 0) { int s = 0; for (int k = 0; k < T_; k++) { offs[k] = s; s += hist[k]; } }
    __syncthreads();
    for (int i = tid; i < T_; i += 256) hist[i] = 0;
    __syncthreads();
    for (int i = tid; i < B_; i += 256) {
        int key = T_ - 1 - seq_lens[i];
        g_order[offs[key] + atomicAdd(&hist[key], 1)] = i;
    }
}

__global__ void __launch_bounds__(256, 1) xproj_mma_kernel(
    const int* __restrict__ item_his, const int* __restrict__ seq_lens,
    const float* __restrict__ emb,
    const float* __restrict__ gk, const float* __restrict__ gb,
    const float* __restrict__ ck, const float* __restrict__ cb)
{
    extern __shared__ char dynsmem[];

    if (blockIdx.x == 2048) { sort_body(seq_lens, dynsmem); return; }

    float*         sBias = (float*)(dynsmem + BIAS_OFF);
    __nv_bfloat16* sAh   = (__nv_bfloat16*)(dynsmem + AH_OFF);
    __nv_bfloat16* sAl   = (__nv_bfloat16*)(dynsmem + AL_OFF);
    __nv_bfloat16* sBh   = (__nv_bfloat16*)(dynsmem + BH_OFF);
    __nv_bfloat16* sBl   = (__nv_bfloat16*)(dynsmem + BL_OFF);

    int b  = blockIdx.x >> 1;
    int t0 = (blockIdx.x & 1) << 7;
    if (t0 >= seq_lens[b]) return;

    int tid = threadIdx.x;

    for (int i = tid; i < GC; i += 256) sBias[i] = (i < 256) ? gb[i] : cb[i - 256];

    {
        int r = tid >> 1, half = tid & 1;
        int item = item_his[b * T_ + t0 + r];
        const float4* e4 = reinterpret_cast<const float4*>(emb + (size_t)item * D_ + half * 32);
        #pragma unroll
        for (int q = 0; q < 8; q++) {
            float4 v = e4[q];
            float f[4] = {v.x, v.y, v.z, v.w};
            int c0 = half * 32 + q * 4;
            #pragma unroll
            for (int i = 0; i < 2; i++) {
                uint32_t lo;
                uint32_t hi = split_pack(f[2*i], f[2*i+1], lo);
                *reinterpret_cast<uint32_t*>(&sAh[r * SA + c0 + 2*i]) = hi;
                *reinterpret_cast<uint32_t*>(&sAl[r * SA + c0 + 2*i]) = lo;
            }
        }
    }
    for (int idx = tid; idx < D_ * GC; idx += 256) {
        int k = idx / GC, n = idx - k * GC;
        float w = (n < 256) ? gk[k * 256 + n] : ck[k * 128 + (n - 256)];
        __nv_bfloat16 h = __float2bfloat16(w);
        sBh[n * SA + k] = h;
        sBl[n * SA + k] = __float2bfloat16(w - __bfloat162float(h));
    }
    __syncthreads();

    int wid = tid >> 5, lane = tid & 31;
    int gid = lane >> 2, tig = lane & 3;
    int m0 = wid * 16;

    uint32_t ah[4][4], al[4][4];
    #pragma unroll
    for (int ks = 0; ks < 4; ks++) {
        int c = ks * 16 + 2 * tig;
        ah[ks][0] = *reinterpret_cast<const uint32_t*>(&sAh[(m0+gid)   * SA + c]);
        ah[ks][1] = *reinterpret_cast<const uint32_t*>(&sAh[(m0+gid+8) * SA + c]);
        ah[ks][2] = *reinterpret_cast<const uint32_t*>(&sAh[(m0+gid)   * SA + c + 8]);
        ah[ks][3] = *reinterpret_cast<const uint32_t*>(&sAh[(m0+gid+8) * SA + c + 8]);
        al[ks][0] = *reinterpret_cast<const uint32_t*>(&sAl[(m0+gid)   * SA + c]);
        al[ks][1] = *reinterpret_cast<const uint32_t*>(&sAl[(m0+gid+8) * SA + c]);
        al[ks][2] = *reinterpret_cast<const uint32_t*>(&sAl[(m0+gid)   * SA + c + 8]);
        al[ks][3] = *reinterpret_cast<const uint32_t*>(&sAl[(m0+gid+8) * SA + c + 8]);
    }

    float* outbase = g_xproj + ((size_t)b * T_ + t0) * GC;

    for (int nt = 0; nt < 48; nt += 2) {
        float acc0[4] = {0.f, 0.f, 0.f, 0.f};
        float acc1[4] = {0.f, 0.f, 0.f, 0.f};
        #pragma unroll
        for (int ks = 0; ks < 4; ks++) {
            int c = ks * 16 + 2 * tig;
            int n0 = (nt * 8 + gid) * SA, n1 = ((nt + 1) * 8 + gid) * SA;
            uint32_t bh00 = *reinterpret_cast<const uint32_t*>(&sBh[n0 + c]);
            uint32_t bh01 = *reinterpret_cast<const uint32_t*>(&sBh[n0 + c + 8]);
            uint32_t bl00 = *reinterpret_cast<const uint32_t*>(&sBl[n0 + c]);
            uint32_t bl01 = *reinterpret_cast<const uint32_t*>(&sBl[n0 + c + 8]);
            uint32_t bh10 = *reinterpret_cast<const uint32_t*>(&sBh[n1 + c]);
            uint32_t bh11 = *reinterpret_cast<const uint32_t*>(&sBh[n1 + c + 8]);
            uint32_t bl10 = *reinterpret_cast<const uint32_t*>(&sBl[n1 + c]);
            uint32_t bl11 = *reinterpret_cast<const uint32_t*>(&sBl[n1 + c + 8]);
            mma16816(acc0, ah[ks], bh00, bh01);
            mma16816(acc1, ah[ks], bh10, bh11);
            mma16816(acc0, ah[ks], bl00, bl01);
            mma16816(acc1, ah[ks], bl10, bl11);
            mma16816(acc0, al[ks], bh00, bh01);
            mma16816(acc1, al[ks], bh10, bh11);
        }
        #pragma unroll
        for (int p = 0; p < 2; p++) {
            float* acc = p ? acc1 : acc0;
            int ncol = (nt + p) * 8 + 2 * tig;
            float2 bias = *reinterpret_cast<const float2*>(&sBias[ncol]);
            float2 o0 = {acc[0] + bias.x, acc[1] + bias.y};
            float2 o1 = {acc[2] + bias.x, acc[3] + bias.y};
            *reinterpret_cast<float2*>(outbase + (size_t)(m0 + gid)     * GC + ncol) = o0;
            *reinterpret_cast<float2*>(outbase + (size_t)(m0 + gid + 8) * GC + ncol) = o1;
        }
    }
}

// ---------------- Phase B: tensor-core GRU ----------------
// 128 CTAs x 8 rows, 512 threads (16 warps). h kept in A-fragment layout in smem.
// Weights-hi in registers (48/thread); weights-lo streamed from smem.
static constexpr int OFF_BGH  = 0;        // u64[32nt][8ks][32ln]  65536 B
static constexpr int OFF_BGL  = 65536;
static constexpr int OFF_BCH  = 131072;   // u64[16][8][32]        32768 B
static constexpr int OFF_BCL  = 163840;
static constexpr int OFF_AH   = 196608;   // u32[8ks][32ln][4reg]  4096 B
static constexpr int OFF_AL   = 200704;
static constexpr int OFF_RH   = 204800;
static constexpr int OFF_RL   = 208896;
static constexpr int OFF_H    = 212992;   // f32[8][132]           4224 B
static constexpr int OFF_U    = 217216;
static constexpr int OFF_META = 221440;   // srow[8], slen[8]
static constexpr int G_SMEM   = 221504;
#define HS 132

__global__ void __launch_bounds__(512, 1) gru_mma_kernel(
    const int* __restrict__ seq_lens,
    const float* __restrict__ gk, const float* __restrict__ ck,
    float* __restrict__ out)
{
    extern __shared__ char dynsmem[];
    uint2* sBgH = (uint2*)(dynsmem + OFF_BGH);
    uint2* sBgL = (uint2*)(dynsmem + OFF_BGL);
    uint2* sBcH = (uint2*)(dynsmem + OFF_BCH);
    uint2* sBcL = (uint2*)(dynsmem + OFF_BCL);
    uint32_t* sAh = (uint32_t*)(dynsmem + OFF_AH);
    uint32_t* sAl = (uint32_t*)(dynsmem + OFF_AL);
    uint32_t* sRh = (uint32_t*)(dynsmem + OFF_RH);
    uint32_t* sRl = (uint32_t*)(dynsmem + OFF_RL);
    float* sH = (float*)(dynsmem + OFF_H);
    float* sU = (float*)(dynsmem + OFF_U);
    int* srow = (int*)(dynsmem + OFF_META);
    int* slen = srow + 8;

    int tid = threadIdx.x;
    int wid = tid >> 5, lane = tid & 31;
    int gid = lane >> 2, tig = lane & 3;

    // ---- init: B fragments (gate) ----
    for (int idx = tid; idx < 32 * 8 * 32; idx += 512) {
        int nt = idx >> 8, ks = (idx >> 5) & 7, ln = idx & 31;
        int g = ln >> 2, tg = ln & 3;
        int n = 8 * nt + g, k0 = 16 * ks + 2 * tg;
        float w00 = gk[(64 + k0)     * 256 + n];
        float w01 = gk[(64 + k0 + 1) * 256 + n];
        float w10 = gk[(64 + k0 + 8) * 256 + n];
        float w11 = gk[(64 + k0 + 9) * 256 + n];
        uint32_t lo0, lo1;
        uint32_t hi0 = split_pack(w00, w01, lo0);
        uint32_t hi1 = split_pack(w10, w11, lo1);
        sBgH[idx] = make_uint2(hi0, hi1);
        sBgL[idx] = make_uint2(lo0, lo1);
    }
    // ---- init: B fragments (cand) ----
    for (int idx = tid; idx < 16 * 8 * 32; idx += 512) {
        int nt = idx >> 8, ks = (idx >> 5) & 7, ln = idx & 31;
        int g = ln >> 2, tg = ln & 3;
        int n = 8 * nt + g, k0 = 16 * ks + 2 * tg;
        float w00 = ck[(64 + k0)     * 128 + n];
        float w01 = ck[(64 + k0 + 1) * 128 + n];
        float w10 = ck[(64 + k0 + 8) * 128 + n];
        float w11 = ck[(64 + k0 + 9) * 128 + n];
        uint32_t lo0, lo1;
        uint32_t hi0 = split_pack(w00, w01, lo0);
        uint32_t hi1 = split_pack(w10, w11, lo1);
        sBcH[idx] = make_uint2(hi0, hi1);
        sBcL[idx] = make_uint2(lo0, lo1);
    }
    // ---- zero state ----
    for (int i = tid; i < 4 * 1024; i += 512) {
        sAh[i] = 0u; sAl[i] = 0u;
        if (i < 2048) { sRh[i] = 0u; sRl[i] = 0u; }
    }
    for (int i = tid; i < 8 * HS; i += 512) { sH[i] = 0.0f; sU[i] = 0.0f; }
    if (tid < 8) {
        int row = g_order[blockIdx.x * 8 + tid];
        srow[tid] = row;
        slen[tid] = seq_lens[row];
    }
    __syncthreads();

    // ---- register-resident B-hi fragments ----
    int nt0 = 2 * wid, nt1 = 2 * wid + 1;
    uint2 BgH0[8], BgH1[8], BcH[8];
    #pragma unroll
    for (int ks = 0; ks < 8; ks++) {
        BgH0[ks] = sBgH[(nt0 * 8 + ks) * 32 + lane];
        BgH1[ks] = sBgH[(nt1 * 8 + ks) * 32 + lane];
        BcH[ks]  = sBcH[(wid * 8 + ks) * 32 + lane];
    }

    int maxlen = slen[0];
    int mylen  = slen[gid];
    int myxoff = srow[gid] * (T_ * GC);
    int cA0 = 16 * wid + 2 * tig;     // gate cols (pair), nt0
    int cA1 = cA0 + 8;                // nt1
    int j0  = 8 * wid + 2 * tig;      // cand col pair (= hidden unit pair)
    bool isR = (wid < 8);             // gate cols < 128 -> r gate, else u gate

    // frag-store offsets (same-lane property: writer lane == this lane)
    int rhOff = ((wid & 7) * 32 + lane) * 4 + ((wid < 8) ? 0 : 0); // only wid<8 writes: regs 0,2
    int ahOff = ((j0 >> 4) * 32 + lane) * 4 + ((wid & 1) ? 2 : 0);

    for (int t = 0; t < maxlen; t++) {
        bool act = (t < mylen);
        int base = myxoff + t * GC;

        // prefetch gate x-projections
        float2 xg0 = make_float2(0.f, 0.f), xg1 = make_float2(0.f, 0.f);
        if (act) {
            xg0 = *reinterpret_cast<const float2*>(&g_xproj[base + cA0]);
            xg1 = *reinterpret_cast<const float2*>(&g_xproj[base + cA1]);
        }

        // ---- gate MMA ----
        float a0[4] = {0.f, 0.f, 0.f, 0.f};
        float a1[4] = {0.f, 0.f, 0.f, 0.f};
        #pragma unroll
        for (int ks = 0; ks < 8; ks++) {
            uint4 ah = *reinterpret_cast<const uint4*>(&sAh[(ks * 32 + lane) * 4]);
            uint4 al = *reinterpret_cast<const uint4*>(&sAl[(ks * 32 + lane) * 4]);
            uint2 bl0 = sBgL[(nt0 * 8 + ks) * 32 + lane];
            uint2 bl1 = sBgL[(nt1 * 8 + ks) * 32 + lane];
            const uint32_t* ahp = reinterpret_cast<const uint32_t*>(&ah);
            const uint32_t* alp = reinterpret_cast<const uint32_t*>(&al);
            mma16816(a0, ahp, BgH0[ks].x, BgH0[ks].y);
            mma16816(a1, ahp, BgH1[ks].x, BgH1[ks].y);
            mma16816(a0, alp, BgH0[ks].x, BgH0[ks].y);
            mma16816(a1, alp, BgH1[ks].x, BgH1[ks].y);
            mma16816(a0, ahp, bl0.x, bl0.y);
            mma16816(a1, ahp, bl1.x, bl1.y);
        }

        // ---- gate combine (rows gid only; d[2],d[3] are zero-rows) ----
        float s0 = sigmoidf_(a0[0] + xg0.x);
        float s1 = sigmoidf_(a0[1] + xg0.y);
        float s2 = sigmoidf_(a1[0] + xg1.x);
        float s3 = sigmoidf_(a1[1] + xg1.y);
        if (isR) {
            float2 h01 = *reinterpret_cast<const float2*>(&sH[gid * HS + cA0]);
            float2 h23 = *reinterpret_cast<const float2*>(&sH[gid * HS + cA1]);
            uint32_t lo;
            uint32_t hi = split_pack(s0 * h01.x, s1 * h01.y, lo);
            sRh[rhOff]     = hi; sRl[rhOff]     = lo;
            hi = split_pack(s2 * h23.x, s3 * h23.y, lo);
            sRh[rhOff + 2] = hi; sRl[rhOff + 2] = lo;
        } else {
            *reinterpret_cast<float2*>(&sU[gid * HS + cA0 - 128]) = make_float2(s0, s1);
            *reinterpret_cast<float2*>(&sU[gid * HS + cA1 - 128]) = make_float2(s2, s3);
        }
        __syncthreads();

        // prefetch cand inputs (this thread owns sH/sU[gid][j0..j0+1])
        float2 xc = make_float2(0.f, 0.f);
        if (act) xc = *reinterpret_cast<const float2*>(&g_xproj[base + 256 + j0]);
        float2 uu   = *reinterpret_cast<const float2*>(&sU[gid * HS + j0]);
        float2 hold = *reinterpret_cast<const float2*>(&sH[gid * HS + j0]);

        // ---- cand MMA ----
        float c0[4] = {0.f, 0.f, 0.f, 0.f};
        #pragma unroll
        for (int ks = 0; ks < 8; ks++) {
            uint4 ah = *reinterpret_cast<const uint4*>(&sRh[(ks * 32 + lane) * 4]);
            uint4 al = *reinterpret_cast<const uint4*>(&sRl[(ks * 32 + lane) * 4]);
            uint2 bl = sBcL[(wid * 8 + ks) * 32 + lane];
            const uint32_t* ahp = reinterpret_cast<const uint32_t*>(&ah);
            const uint32_t* alp = reinterpret_cast<const uint32_t*>(&al);
            mma16816(c0, ahp, BcH[ks].x, BcH[ks].y);
            mma16816(c0, alp, BcH[ks].x, BcH[ks].y);
            mma16816(c0, ahp, bl.x, bl.y);
        }

        // ---- update (this thread owns h[gid][j0..j0+1]) ----
        if (act) {
            float cc0 = tanhf_(c0[0] + xc.x);
            float cc1 = tanhf_(c0[1] + xc.y);
            float hn0 = uu.x * hold.x + (1.0f - uu.x) * cc0;
            float hn1 = uu.y * hold.y + (1.0f - uu.y) * cc1;
            *reinterpret_cast<float2*>(&sH[gid * HS + j0]) = make_float2(hn0, hn1);
            uint32_t lo;
            uint32_t hi = split_pack(hn0, hn1, lo);
            sAh[ahOff] = hi;
            sAl[ahOff] = lo;
        }
        __syncthreads();
    }

    // output: thread owns h[gid][j0..j0+1]
    float2 hv = *reinterpret_cast<const float2*>(&sH[gid * HS + j0]);
    *reinterpret_cast<float2*>(&out[(size_t)srow[gid] * H_ + j0]) = hv;
}

// ---------------- launch ----------------
extern "C" void kernel_launch(void* const* d_in, const int* in_sizes, int n_in,
                              void* d_out, int out_size) {
    const int*   item_his = (const int*)  d_in[0];
    const int*   seq_lens = (const int*)  d_in[1];
    const float* emb      = (const float*)d_in[2];
    const float* gk       = (const float*)d_in[3];
    const float* gb       = (const float*)d_in[4];
    const float* ck       = (const float*)d_in[5];
    const float* cb       = (const float*)d_in[6];
    float*       out      = (float*)d_out;

    cudaFuncSetAttribute(xproj_mma_kernel, cudaFuncAttributeMaxDynamicSharedMemorySize, PA_SMEM);
    cudaFuncSetAttribute(gru_mma_kernel,   cudaFuncAttributeMaxDynamicSharedMemorySize, G_SMEM);

    xproj_mma_kernel<<<2049, 256, PA_SMEM>>>(item_his, seq_lens, emb, gk, gb, ck, cb);
    gru_mma_kernel<<<B_ / 8, 512, G_SMEM>>>(seq_lens, gk, ck, out);
}